// round 3
// baseline (speedup 1.0000x reference)
#include <cuda_runtime.h>
#include <cuda_bf16.h>
#include <math.h>

#define NN 50000
#define EE 800000
#define OUTC 40

__device__ __align__(128) float g_scratch[29000000];

// ======================= edge_index dtype handling =========================
// If edge_index is int64 (values < 2^31), every odd 32-bit word of the first
// EE entries is 0. If int32, those words are random node ids (some nonzero).

__global__ void detect_kernel(const int* __restrict__ w, int* flag64) {
    int any = 0;
    for (int i = blockIdx.x * blockDim.x + threadIdx.x; i < EE; i += gridDim.x * blockDim.x)
        any |= w[2 * i + 1];
    if (any) atomicAnd(flag64, 0);
}

__global__ void convert_kernel(const int* __restrict__ w, const int* __restrict__ flag64,
                               int* __restrict__ rowA, int* __restrict__ colA) {
    int e = blockIdx.x * blockDim.x + threadIdx.x;
    if (e >= EE) return;
    if (*flag64) {
        rowA[e] = w[2 * e];
        colA[e] = w[2 * (EE + e)];
    } else {
        rowA[e] = w[e];
        colA[e] = w[EE + e];
    }
}

// ======================= CSR construction =================================

__global__ void init_counts_kernel(int* c1, int* c2, int* flag64) {
    int i = blockIdx.x * blockDim.x + threadIdx.x;
    if (i < NN) { c1[i] = 1; c2[i] = 0; }   // c1 starts at 1 (self-loop)
    if (i == 0) *flag64 = 1;
}

__global__ void hist_kernel(const int* __restrict__ rowA, const int* __restrict__ colA,
                            int* c1, int* c2) {
    int e = blockIdx.x * blockDim.x + threadIdx.x;
    if (e >= EE) return;
    atomicAdd(&c1[colA[e]], 1);
    atomicAdd(&c2[rowA[e]], 1);
}

__device__ void scan_one(const int* __restrict__ cnt, int* __restrict__ off, int n) {
    __shared__ int warpsum[32];
    __shared__ int s_carry;
    const int t = threadIdx.x, lane = t & 31, wid = t >> 5;
    if (t == 0) s_carry = 0;
    __syncthreads();
    for (int base = 0; base < n; base += 8192) {
        int v[8];
        int idx0 = base + t * 8;
#pragma unroll
        for (int i = 0; i < 8; i++) { int id = idx0 + i; v[i] = (id < n) ? cnt[id] : 0; }
        int run = 0;
#pragma unroll
        for (int i = 0; i < 8; i++) { int tmp = v[i]; v[i] = run; run += tmp; }
        int x = run;
#pragma unroll
        for (int d = 1; d < 32; d <<= 1) { int y = __shfl_up_sync(0xffffffffu, x, d); if (lane >= d) x += y; }
        if (lane == 31) warpsum[wid] = x;
        __syncthreads();
        if (wid == 0) {
            int w = warpsum[lane];
#pragma unroll
            for (int d = 1; d < 32; d <<= 1) { int y = __shfl_up_sync(0xffffffffu, w, d); if (lane >= d) w += y; }
            warpsum[lane] = w;
        }
        __syncthreads();
        int warpoff = (wid > 0) ? warpsum[wid - 1] : 0;
        int texc = warpoff + (x - run);
        int carry = s_carry;
#pragma unroll
        for (int i = 0; i < 8; i++) { int id = idx0 + i; if (id < n) off[id] = carry + texc + v[i]; }
        __syncthreads();
        if (t == 0) s_carry = carry + warpsum[31];
        __syncthreads();
    }
    if (t == 0) off[n] = s_carry;
    __syncthreads();
}

__global__ void scan_kernel(const int* c1, int* o1, const int* c2, int* o2) {
    scan_one(c1, o1, NN);
    scan_one(c2, o2, NN);
}

__global__ void init_cursors_kernel(const int* off1, const int* off2,
                                    int* cur1, int* cur2, int* csr1) {
    int i = blockIdx.x * blockDim.x + threadIdx.x;
    if (i >= NN) return;
    int o = off1[i];
    cur1[i] = o + 1;
    csr1[o] = i;            // self-loop slot: src = i
    cur2[i] = off2[i];
}

__global__ void fill_kernel(const int* __restrict__ rowA, const int* __restrict__ colA,
                            int* cur1, int* csr1,
                            int* cur2, int* csr2c, int* csr2e) {
    int e = blockIdx.x * blockDim.x + threadIdx.x;
    if (e >= EE) return;
    int r = rowA[e];
    int c = colA[e];
    int p = atomicAdd(&cur1[c], 1);
    csr1[p] = r;
    int q = atomicAdd(&cur2[r], 1);
    csr2c[q] = c;
    csr2e[q] = e;
}

// ======================= GEMM (K = 128 fixed) ===============================
// out[n][ocol+col] = sum_k A[n][k] * W[col*ldw + woff + k] + bias[col]

template <int TC>
__global__ void __launch_bounds__(128)
gemm_k128(const float* __restrict__ A, const float* __restrict__ W,
          int ldw, int woff, const float* __restrict__ bias,
          float* __restrict__ out, int opitch, int ocol, int nrows) {
    constexpr int CT = TC / 16;
    constexpr int PA = 68;
    constexpr int PW = TC + 4;
    __shared__ float sA[32 * PA];
    __shared__ float sW[32 * PW];
    const int tid = threadIdx.x;
    const int trow = tid >> 4;
    const int tcol = tid & 15;
    const int r0 = blockIdx.x * 64;

    float acc[8][CT];
#pragma unroll
    for (int i = 0; i < 8; i++)
#pragma unroll
        for (int j = 0; j < CT; j++) acc[i][j] = 0.f;

    for (int kb = 0; kb < 128; kb += 32) {
        __syncthreads();
#pragma unroll
        for (int i = 0; i < 16; i++) {
            int idx = tid + i * 128;
            int row = idx >> 5, kk = idx & 31;
            int gr = r0 + row;
            sA[kk * PA + row] = (gr < nrows) ? A[(size_t)gr * 128 + kb + kk] : 0.f;
        }
#pragma unroll
        for (int i = 0; i < (TC * 32) / 128; i++) {
            int idx = tid + i * 128;
            int col = idx >> 5, kk = idx & 31;
            sW[kk * PW + col] = W[(size_t)col * ldw + woff + kb + kk];
        }
        __syncthreads();
#pragma unroll
        for (int kk = 0; kk < 32; kk++) {
            float a[8], w[CT];
            float4 a0 = *(const float4*)&sA[kk * PA + trow * 8];
            float4 a1 = *(const float4*)&sA[kk * PA + trow * 8 + 4];
            a[0] = a0.x; a[1] = a0.y; a[2] = a0.z; a[3] = a0.w;
            a[4] = a1.x; a[5] = a1.y; a[6] = a1.z; a[7] = a1.w;
#pragma unroll
            for (int j = 0; j < CT; j += 4) {
                float4 wv = *(const float4*)&sW[kk * PW + tcol * CT + j];
                w[j] = wv.x; w[j + 1] = wv.y; w[j + 2] = wv.z; w[j + 3] = wv.w;
            }
#pragma unroll
            for (int i = 0; i < 8; i++)
#pragma unroll
                for (int j = 0; j < CT; j++) acc[i][j] = fmaf(a[i], w[j], acc[i][j]);
        }
    }
#pragma unroll
    for (int i = 0; i < 8; i++) {
        int gr = r0 + trow * 8 + i;
        if (gr < nrows) {
#pragma unroll
            for (int j = 0; j < CT; j++) {
                int col = tcol * CT + j;
                float b = bias ? bias[col] : 0.f;
                out[(size_t)gr * opitch + ocol + col] = acc[i][j] + b;
            }
        }
    }
}

// ======================= GAT pieces ========================================

__global__ void attn_kernel(const float* __restrict__ h, const float* __restrict__ as,
                            const float* __restrict__ ad,
                            float* __restrict__ asrc, float* __restrict__ adst) {
    int tid = blockIdx.x * blockDim.x + threadIdx.x;
    if (tid >= NN * 8) return;
    int n = tid >> 3, hd = tid & 7;
    const float* hp = h + (size_t)n * 128 + hd * 16;
    const float* ap = as + hd * 16;
    const float* dp = ad + hd * 16;
    float s1 = 0.f, s2 = 0.f;
#pragma unroll
    for (int c = 0; c < 16; c++) {
        float v = hp[c];
        s1 = fmaf(v, ap[c], s1);
        s2 = fmaf(v, dp[c], s2);
    }
    asrc[tid] = s1;
    adst[tid] = s2;
}

__global__ void sm_stats_kernel(const float* __restrict__ asrc, const float* __restrict__ adst,
                                const int* __restrict__ off, const int* __restrict__ csr,
                                float* __restrict__ m, float* __restrict__ den) {
    int tid = blockIdx.x * blockDim.x + threadIdx.x;
    if (tid >= NN * 8) return;
    int n = tid >> 3, hd = tid & 7;
    float ad = adst[tid];
    int s0 = off[n], s1 = off[n + 1];
    float mm = -INFINITY;
    for (int i = s0; i < s1; i++) {
        int s = csr[i];
        float e = asrc[s * 8 + hd] + ad;
        e = (e >= 0.f) ? e : 0.2f * e;
        mm = fmaxf(mm, e);
    }
    float dd = 0.f;
    for (int i = s0; i < s1; i++) {
        int s = csr[i];
        float e = asrc[s * 8 + hd] + ad;
        e = (e >= 0.f) ? e : 0.2f * e;
        dd += __expf(e - mm);
    }
    m[tid] = mm;
    den[tid] = dd;
}

// one warp per node; lane owns 4 contiguous features (head = lane>>2)
__global__ void gat_aggregate(const float* __restrict__ hfeat,
                              const float* __restrict__ asrc, const float* __restrict__ adst,
                              const float* __restrict__ m, const float* __restrict__ den,
                              const int* __restrict__ off, const int* __restrict__ csr,
                              const float* __restrict__ bg, float* __restrict__ outp) {
    int gw = (blockIdx.x * blockDim.x + threadIdx.x) >> 5;
    if (gw >= NN) return;
    int lane = threadIdx.x & 31;
    int head = lane >> 2;
    float ad = adst[gw * 8 + head];
    float mm = m[gw * 8 + head];
    float inv = 1.f / (den[gw * 8 + head] + 1e-16f);
    float4 acc = make_float4(0.f, 0.f, 0.f, 0.f);
    int s0 = off[gw], s1 = off[gw + 1];
    for (int i = s0; i < s1; i++) {
        int s = csr[i];
        float e = asrc[s * 8 + head] + ad;
        e = (e >= 0.f) ? e : 0.2f * e;
        float alpha = __expf(e - mm) * inv;
        float4 hv = *(const float4*)&hfeat[(size_t)s * 128 + lane * 4];
        acc.x = fmaf(hv.x, alpha, acc.x);
        acc.y = fmaf(hv.y, alpha, acc.y);
        acc.z = fmaf(hv.z, alpha, acc.z);
        acc.w = fmaf(hv.w, alpha, acc.w);
    }
    float4 bgv = *(const float4*)&bg[lane * 4];
    acc.x += bgv.x; acc.y += bgv.y; acc.z += bgv.z; acc.w += bgv.w;
    *(float4*)&outp[(size_t)gw * 128 + lane * 4] = acc;
}

// ======================= BatchNorm =========================================

__global__ void zero_stats_kernel(float* sums, float* sq) {
    int f = threadIdx.x;
    if (f < 128) { sums[f] = 0.f; sq[f] = 0.f; }
}

__global__ void bn_sum_kernel(const float* __restrict__ x, float* __restrict__ sums,
                              int nrows, int F) {
    int f = threadIdx.x;
    float s = 0.f;
    for (int r = blockIdx.x; r < nrows; r += gridDim.x) s += x[(size_t)r * F + f];
    atomicAdd(&sums[f], s);
}

__global__ void bn_sqsum_kernel(const float* __restrict__ x, const float* __restrict__ mean,
                                float* __restrict__ sq, int nrows, int F) {
    int f = threadIdx.x;
    float mu = mean[f];
    float s = 0.f;
    for (int r = blockIdx.x; r < nrows; r += gridDim.x) {
        float d = x[(size_t)r * F + f] - mu;
        s = fmaf(d, d, s);
    }
    atomicAdd(&sq[f], s);
}

__global__ void bn_fin_mean_kernel(const float* sums, float* mean, int F, float invN) {
    int f = threadIdx.x;
    if (f < F) mean[f] = sums[f] * invN;
}

__global__ void bn_fin_rstd_kernel(const float* sq, float* rstd, int F, float invN) {
    int f = threadIdx.x;
    if (f < F) rstd[f] = rsqrtf(sq[f] * invN + 1e-5f);
}

// BN + ELU over (N,128)
__global__ void bn_elu_kernel(const float* __restrict__ x, const float* __restrict__ mean,
                              const float* __restrict__ rstd, const float* __restrict__ gamma,
                              const float* __restrict__ beta, float* __restrict__ out, int total) {
    int i = (blockIdx.x * blockDim.x + threadIdx.x) * 4;
    if (i >= total) return;
    float4 v = *(const float4*)&x[i];
    int f = i & 127;
    float r[4] = {v.x, v.y, v.z, v.w};
#pragma unroll
    for (int k = 0; k < 4; k++) {
        int ff = f + k;
        float t = (r[k] - mean[ff]) * rstd[ff] * gamma[ff] + beta[ff];
        r[k] = (t > 0.f) ? t : expm1f(t);
    }
    *(float4*)&out[i] = make_float4(r[0], r[1], r[2], r[3]);
}

// ======================= Edge scorer + gumbel gate =========================

__global__ void edge_logits_kernel(const float* __restrict__ prpc,
                                   const int* __restrict__ rowA, const int* __restrict__ colA,
                                   const float* __restrict__ gumbel,
                                   const float* __restrict__ bs1,
                                   const float* __restrict__ ws2,
                                   const float* __restrict__ bs2,
                                   float* __restrict__ wout, float* __restrict__ lrout) {
    __shared__ float sw2[64];
    __shared__ float sb1[64];
    if (threadIdx.x < 64) { sw2[threadIdx.x] = ws2[threadIdx.x]; sb1[threadIdx.x] = bs1[threadIdx.x]; }
    __syncthreads();
    int ge = (blockIdx.x * blockDim.x + threadIdx.x) >> 5;
    if (ge >= EE) return;
    int lane = threadIdx.x & 31;
    int r = rowA[ge];
    int c = colA[ge];
    float p0 = prpc[(size_t)r * 128 + lane]      + prpc[(size_t)c * 128 + 64 + lane] + sb1[lane];
    float p1 = prpc[(size_t)r * 128 + 32 + lane] + prpc[(size_t)c * 128 + 96 + lane] + sb1[32 + lane];
    p0 = fmaxf(p0, 0.f);
    p1 = fmaxf(p1, 0.f);
    float part = p0 * sw2[lane] + p1 * sw2[32 + lane];
#pragma unroll
    for (int d = 16; d; d >>= 1) part += __shfl_xor_sync(0xffffffffu, part, d);
    if (lane == 0) {
        float lr = part + bs2[0];
        lrout[ge] = lr;
        float g0 = gumbel[2 * (size_t)ge];
        float g1 = gumbel[2 * (size_t)ge + 1];
        wout[ge] = (lr + g1 > g0) ? 1.f : 0.f;
    }
}

// h_sparse = h_base + segment_sum(weights * h_base[col], row)
__global__ void sparse_agg_kernel(const float* __restrict__ hbase,
                                  const int* __restrict__ off2,
                                  const int* __restrict__ col, const int* __restrict__ eid,
                                  const float* __restrict__ w, float* __restrict__ outp) {
    int gw = (blockIdx.x * blockDim.x + threadIdx.x) >> 5;
    if (gw >= NN) return;
    int lane = threadIdx.x & 31;
    float4 acc = *(const float4*)&hbase[(size_t)gw * 128 + lane * 4];
    int s0 = off2[gw], s1 = off2[gw + 1];
    for (int i = s0; i < s1; i++) {
        int e = eid[i];
        if (w[e] != 0.f) {
            int c = col[i];
            float4 hv = *(const float4*)&hbase[(size_t)c * 128 + lane * 4];
            acc.x += hv.x; acc.y += hv.y; acc.z += hv.z; acc.w += hv.w;
        }
    }
    *(float4*)&outp[(size_t)gw * 128 + lane * 4] = acc;
}

// ======================= Classifier head ===================================

__global__ void __launch_bounds__(256)
classifier_kernel(const float* __restrict__ cpre, const float* __restrict__ mean,
                  const float* __restrict__ rstd, const float* __restrict__ gc,
                  const float* __restrict__ bec, const float* __restrict__ Wc2,
                  const float* __restrict__ bc2, float* __restrict__ outls) {
    __shared__ float sW[64 * 64];   // sW[f*64 + j], j>=40 zero
    __shared__ float sb[40];
    __shared__ float sc[8][64];
    for (int idx = threadIdx.x; idx < 64 * 64; idx += blockDim.x) {
        int f = idx >> 6, j = idx & 63;
        sW[idx] = (j < 40) ? Wc2[j * 64 + f] : 0.f;
    }
    if (threadIdx.x < 40) sb[threadIdx.x] = bc2[threadIdx.x];
    __syncthreads();
    int gw = (blockIdx.x * blockDim.x + threadIdx.x) >> 5;
    int lane = threadIdx.x & 31;
    int wib = threadIdx.x >> 5;
    if (gw >= NN) return;
    float v0 = cpre[(size_t)gw * 64 + lane];
    float v1 = cpre[(size_t)gw * 64 + 32 + lane];
    int f0 = lane, f1 = lane + 32;
    sc[wib][lane]      = fmaxf((v0 - mean[f0]) * rstd[f0] * gc[f0] + bec[f0], 0.f);
    sc[wib][lane + 32] = fmaxf((v1 - mean[f1]) * rstd[f1] * gc[f1] + bec[f1], 0.f);
    __syncwarp();
    float l0 = sb[lane];
    float l1 = (lane < 8) ? sb[lane + 32] : 0.f;
#pragma unroll
    for (int f = 0; f < 64; f++) {
        float cv = sc[wib][f];
        l0 = fmaf(cv, sW[f * 64 + lane], l0);
        l1 = fmaf(cv, sW[f * 64 + lane + 32], l1);
    }
    float mx = fmaxf(l0, (lane < 8) ? l1 : -INFINITY);
#pragma unroll
    for (int d = 16; d; d >>= 1) mx = fmaxf(mx, __shfl_xor_sync(0xffffffffu, mx, d));
    float s = expf(l0 - mx) + ((lane < 8) ? expf(l1 - mx) : 0.f);
#pragma unroll
    for (int d = 16; d; d >>= 1) s += __shfl_xor_sync(0xffffffffu, s, d);
    float lse = mx + logf(s);
    outls[(size_t)gw * 40 + lane] = l0 - lse;
    if (lane < 8) outls[(size_t)gw * 40 + 32 + lane] = l1 - lse;
}

// ======================= Host orchestration ================================

extern "C" void kernel_launch(void* const* d_in, const int* in_sizes, int n_in,
                              void* d_out, int out_size) {
    (void)in_sizes; (void)n_in; (void)out_size;

    float* S = nullptr;
    cudaGetSymbolAddress((void**)&S, g_scratch);

    float* bufA = S;                       // N*128
    float* bufH = S + 6400000;             // N*128
    float* bufG = S + 12800000;            // N*128
    float* bufC = S + 19200000;            // N*64
    float* asrc = S + 22400000;            // N*8
    float* adst = S + 22800000;
    float* mArr = S + 23200000;
    float* dArr = S + 23600000;
    float* sums = S + 24000000;
    float* sq   = sums + 128;
    float* mean = sums + 256;
    float* rstd = sums + 384;
    int* ip    = (int*)(S + 24000512);
    int* rowA  = ip;                       // EE
    int* colA  = rowA + EE;                // EE
    int* off1  = colA + EE;                // NN+1
    int* off2  = off1 + (NN + 1);          // NN+1
    int* cur1  = off2 + (NN + 1);
    int* cur2  = cur1 + NN;
    int* cnt1  = cur2 + NN;
    int* cnt2  = cnt1 + NN;
    int* csr1  = cnt2 + NN;                // EE + NN
    int* csr2c = csr1 + (EE + NN);         // EE
    int* csr2e = csr2c + EE;               // EE
    int* flag64 = csr2e + EE;              // 1

    const float* x      = (const float*)d_in[0];
    const int*   eiw    = (const int*)d_in[1];     // raw 32-bit words of edge_index
    const float* gumbel = (const float*)d_in[2];
    const float* W_res  = (const float*)d_in[3];
    const float* b_res  = (const float*)d_in[4];
    const float* Wg1    = (const float*)d_in[5];
    const float* as1    = (const float*)d_in[6];
    const float* ad1    = (const float*)d_in[7];
    const float* bg1    = (const float*)d_in[8];
    const float* g1     = (const float*)d_in[9];
    const float* be1    = (const float*)d_in[10];
    const float* Wg2    = (const float*)d_in[11];
    const float* as2    = (const float*)d_in[12];
    const float* ad2    = (const float*)d_in[13];
    const float* bg2    = (const float*)d_in[14];
    const float* g2     = (const float*)d_in[15];
    const float* be2    = (const float*)d_in[16];
    const float* Ws1    = (const float*)d_in[17];
    const float* bs1    = (const float*)d_in[18];
    const float* Ws2    = (const float*)d_in[19];
    const float* bs2    = (const float*)d_in[20];
    const float* Wc1    = (const float*)d_in[21];
    const float* bc1    = (const float*)d_in[22];
    const float* gc     = (const float*)d_in[23];
    const float* bec    = (const float*)d_in[24];
    const float* Wc2    = (const float*)d_in[25];
    const float* bc2    = (const float*)d_in[26];

    float* out_ls = (float*)d_out;                    // N*40
    float* out_w  = out_ls + (size_t)NN * OUTC;       // E
    float* out_lr = out_w + EE;                       // E

    const int NB   = (NN + 255) / 256;
    const int EB   = (EE + 255) / 256;
    const int NHB  = (NN * 8 + 255) / 256;
    const int WRPN = (NN * 32) / 256;
    const int WRPE = (EE * 32) / 256;
    const int GEMG = (NN + 63) / 64;
    const float invN = 1.f / (float)NN;

    // ---- edge_index dtype probe + convert ----
    init_counts_kernel<<<NB, 256>>>(cnt1, cnt2, flag64);
    detect_kernel<<<256, 256>>>(eiw, flag64);
    convert_kernel<<<EB, 256>>>(eiw, flag64, rowA, colA);

    // ---- CSR build ----
    hist_kernel<<<EB, 256>>>(rowA, colA, cnt1, cnt2);
    scan_kernel<<<1, 1024>>>(cnt1, off1, cnt2, off2);
    init_cursors_kernel<<<NB, 256>>>(off1, off2, cur1, cur2, csr1);
    fill_kernel<<<EB, 256>>>(rowA, colA, cur1, csr1, cur2, csr2c, csr2e);

    // ---- x_proj ----
    gemm_k128<128><<<GEMG, 128>>>(x, W_res, 128, 0, b_res, bufA, 128, 0, NN);

    // ---- GAT layer 1 ----
    gemm_k128<128><<<GEMG, 128>>>(bufA, Wg1, 128, 0, nullptr, bufH, 128, 0, NN);
    attn_kernel<<<NHB, 256>>>(bufH, as1, ad1, asrc, adst);
    sm_stats_kernel<<<NHB, 256>>>(asrc, adst, off1, csr1, mArr, dArr);
    gat_aggregate<<<WRPN, 256>>>(bufH, asrc, adst, mArr, dArr, off1, csr1, bg1, bufG);
    zero_stats_kernel<<<1, 128>>>(sums, sq);
    bn_sum_kernel<<<512, 128>>>(bufG, sums, NN, 128);
    bn_fin_mean_kernel<<<1, 128>>>(sums, mean, 128, invN);
    bn_sqsum_kernel<<<512, 128>>>(bufG, mean, sq, NN, 128);
    bn_fin_rstd_kernel<<<1, 128>>>(sq, rstd, 128, invN);
    bn_elu_kernel<<<(NN * 32 + 255) / 256, 256>>>(bufG, mean, rstd, g1, be1, bufA, NN * 128);

    // ---- GAT layer 2 ----
    gemm_k128<128><<<GEMG, 128>>>(bufA, Wg2, 128, 0, nullptr, bufH, 128, 0, NN);
    attn_kernel<<<NHB, 256>>>(bufH, as2, ad2, asrc, adst);
    sm_stats_kernel<<<NHB, 256>>>(asrc, adst, off1, csr1, mArr, dArr);
    gat_aggregate<<<WRPN, 256>>>(bufH, asrc, adst, mArr, dArr, off1, csr1, bg2, bufG);
    zero_stats_kernel<<<1, 128>>>(sums, sq);
    bn_sum_kernel<<<512, 128>>>(bufG, sums, NN, 128);
    bn_fin_mean_kernel<<<1, 128>>>(sums, mean, 128, invN);
    bn_sqsum_kernel<<<512, 128>>>(bufG, mean, sq, NN, 128);
    bn_fin_rstd_kernel<<<1, 128>>>(sq, rstd, 128, invN);
    bn_elu_kernel<<<(NN * 32 + 255) / 256, 256>>>(bufG, mean, rstd, g2, be2, bufA, NN * 128);
    // bufA = h_base

    // ---- edge scorer ----
    gemm_k128<64><<<GEMG, 128>>>(bufA, Ws1, 256, 0,   nullptr, bufH, 128, 0,  NN);
    gemm_k128<64><<<GEMG, 128>>>(bufA, Ws1, 256, 128, nullptr, bufH, 128, 64, NN);
    edge_logits_kernel<<<WRPE, 256>>>(bufH, rowA, colA, gumbel, bs1, Ws2, bs2, out_w, out_lr);

    // ---- sparse aggregation ----
    sparse_agg_kernel<<<WRPN, 256>>>(bufA, off2, csr2c, csr2e, out_w, bufG);

    // ---- classifier ----
    gemm_k128<64><<<GEMG, 128>>>(bufG, Wc1, 128, 0, bc1, bufC, 64, 0, NN);
    zero_stats_kernel<<<1, 128>>>(sums, sq);
    bn_sum_kernel<<<512, 64>>>(bufC, sums, NN, 64);
    bn_fin_mean_kernel<<<1, 64>>>(sums, mean, 64, invN);
    bn_sqsum_kernel<<<512, 64>>>(bufC, mean, sq, NN, 64);
    bn_fin_rstd_kernel<<<1, 64>>>(sq, rstd, 64, invN);
    classifier_kernel<<<WRPN, 256>>>(bufC, mean, rstd, gc, bec, Wc2, bc2, out_ls);
}

// round 4
// speedup vs baseline: 1.1058x; 1.1058x over previous
#include <cuda_runtime.h>
#include <cuda_bf16.h>
#include <math.h>

#define NN 50000
#define EE 800000
#define OUTC 40
#define NTILE 196            // ceil(50000/256)

__device__ __align__(128) float g_scratch[29000000];

#define PACK2(dst, lo, hi) asm("mov.b64 %0, {%1, %2};" : "=l"(dst) : "f"(lo), "f"(hi))
#define UNPK2(lo, hi, v)   asm("mov.b64 {%0, %1}, %2;" : "=f"(lo), "=f"(hi) : "l"(v))
#define FMA2(acc, a, b)    asm("fma.rn.f32x2 %0, %1, %2, %0;" : "+l"(acc) : "l"(a), "l"(b))

// ======================= edge_index dtype handling =========================
__global__ void detect_kernel(const int* __restrict__ w, int* flag64) {
    int any = 0;
    for (int i = blockIdx.x * blockDim.x + threadIdx.x; i < EE; i += gridDim.x * blockDim.x)
        any |= w[2 * i + 1];
    if (any) atomicAnd(flag64, 0);
}

__global__ void convert_kernel(const int* __restrict__ w, const int* __restrict__ flag64,
                               int* __restrict__ rowA, int* __restrict__ colA) {
    int e = blockIdx.x * blockDim.x + threadIdx.x;
    if (e >= EE) return;
    if (*flag64) {
        rowA[e] = w[2 * e];
        colA[e] = w[2 * (EE + e)];
    } else {
        rowA[e] = w[e];
        colA[e] = w[EE + e];
    }
}

// ======================= CSR construction =================================
__global__ void init_counts_kernel(int* c1, int* c2, int* flag64) {
    int i = blockIdx.x * blockDim.x + threadIdx.x;
    if (i < NN) { c1[i] = 1; c2[i] = 0; }   // c1 starts at 1 (self-loop)
    if (i == 0) *flag64 = 1;
}

__global__ void hist_kernel(const int* __restrict__ rowA, const int* __restrict__ colA,
                            int* c1, int* c2) {
    int e = blockIdx.x * blockDim.x + threadIdx.x;
    if (e >= EE) return;
    atomicAdd(&c1[colA[e]], 1);
    atomicAdd(&c2[rowA[e]], 1);
}

// ---- parallel 3-phase exclusive scan over two arrays (gridDim.y selects) ----
__global__ void scan_p1(const int* __restrict__ cnt1, const int* __restrict__ cnt2,
                        int* __restrict__ btot) {
    const int* cnt = blockIdx.y ? cnt2 : cnt1;
    __shared__ int sw[8];
    int idx = blockIdx.x * 256 + threadIdx.x;
    int v = (idx < NN) ? cnt[idx] : 0;
#pragma unroll
    for (int d = 16; d; d >>= 1) v += __shfl_xor_sync(0xffffffffu, v, d);
    if ((threadIdx.x & 31) == 0) sw[threadIdx.x >> 5] = v;
    __syncthreads();
    if (threadIdx.x == 0) {
        int s = 0;
#pragma unroll
        for (int i = 0; i < 8; i++) s += sw[i];
        btot[blockIdx.y * (NTILE + 1) + blockIdx.x] = s;
    }
}

__global__ void scan_p2(int* __restrict__ btot) {
    // one block per array: exclusive scan of NTILE totals (NTILE <= 256)
    int* b = btot + blockIdx.y * (NTILE + 1);
    __shared__ int sw[8], sw2[9];
    int t = threadIdx.x, lane = t & 31, wid = t >> 5;
    int v = (t < NTILE) ? b[t] : 0;
    int inc = v;
#pragma unroll
    for (int d = 1; d < 32; d <<= 1) { int y = __shfl_up_sync(0xffffffffu, inc, d); if (lane >= d) inc += y; }
    if (lane == 31) sw[wid] = inc;
    __syncthreads();
    if (t == 0) { sw2[0] = 0; for (int i = 0; i < 8; i++) sw2[i + 1] = sw2[i] + sw[i]; }
    __syncthreads();
    int excl = sw2[wid] + inc - v;
    if (t < NTILE) b[t] = excl;
    if (t == 0) b[NTILE] = sw2[8];
}

__global__ void scan_p3(const int* __restrict__ cnt1, const int* __restrict__ cnt2,
                        const int* __restrict__ btot,
                        int* __restrict__ off1, int* __restrict__ off2) {
    const int* cnt = blockIdx.y ? cnt2 : cnt1;
    int* off = blockIdx.y ? off2 : off1;
    const int* b = btot + blockIdx.y * (NTILE + 1);
    __shared__ int sw[8], sw2[9];
    int t = threadIdx.x, lane = t & 31, wid = t >> 5;
    int idx = blockIdx.x * 256 + t;
    int v = (idx < NN) ? cnt[idx] : 0;
    int inc = v;
#pragma unroll
    for (int d = 1; d < 32; d <<= 1) { int y = __shfl_up_sync(0xffffffffu, inc, d); if (lane >= d) inc += y; }
    if (lane == 31) sw[wid] = inc;
    __syncthreads();
    if (t == 0) { sw2[0] = 0; for (int i = 0; i < 8; i++) sw2[i + 1] = sw2[i] + sw[i]; }
    __syncthreads();
    int excl = b[blockIdx.x] + sw2[wid] + inc - v;
    if (idx < NN) off[idx] = excl;
    if (blockIdx.x == 0 && t == 0) off[NN] = b[NTILE];
}

__global__ void init_cursors_kernel(const int* off1, const int* off2,
                                    int* cur1, int* cur2, int* csr1) {
    int i = blockIdx.x * blockDim.x + threadIdx.x;
    if (i >= NN) return;
    int o = off1[i];
    cur1[i] = o + 1;
    csr1[o] = i;            // self-loop slot: src = i
    cur2[i] = off2[i];
}

__global__ void fill_kernel(const int* __restrict__ rowA, const int* __restrict__ colA,
                            int* cur1, int* csr1,
                            int* cur2, int* csr2c, int* csr2e) {
    int e = blockIdx.x * blockDim.x + threadIdx.x;
    if (e >= EE) return;
    int r = rowA[e];
    int c = colA[e];
    int p = atomicAdd(&cur1[c], 1);
    csr1[p] = r;
    int q = atomicAdd(&cur2[r], 1);
    csr2c[q] = c;
    csr2e[q] = e;
}

// ======================= GEMM (K = 128 fixed, f32x2 FMA) ====================
// out[n][ocol+col] = sum_k A[n][k] * W[col*ldw + woff + k] + bias[col]
// 64 rows x TC cols per block, 128 threads, thread tile 8 rows (4 f32x2 pairs)
// x CT cols.

template <int TC>
__global__ void __launch_bounds__(128)
gemm_k128(const float* __restrict__ A, const float* __restrict__ W,
          int ldw, int woff, const float* __restrict__ bias,
          float* __restrict__ out, int opitch, int ocol, int nrows) {
    constexpr int CT = TC / 16;
    constexpr int PA = 68;
    constexpr int PW = TC + 4;
    __shared__ float sA[32 * PA];
    __shared__ float sW[32 * PW];
    const int tid = threadIdx.x;
    const int trow = tid >> 4;     // 0..7
    const int tcol = tid & 15;     // 0..15
    const int r0 = blockIdx.x * 64;

    unsigned long long acc2[4][CT];   // row-pairs x cols
#pragma unroll
    for (int p = 0; p < 4; p++)
#pragma unroll
        for (int j = 0; j < CT; j++) acc2[p][j] = 0ull;

    for (int kb = 0; kb < 128; kb += 32) {
        __syncthreads();
#pragma unroll
        for (int i = 0; i < 16; i++) {
            int idx = tid + i * 128;
            int row = idx >> 5, kk = idx & 31;
            int gr = r0 + row;
            sA[kk * PA + row] = (gr < nrows) ? A[(size_t)gr * 128 + kb + kk] : 0.f;
        }
#pragma unroll
        for (int i = 0; i < (TC * 32) / 128; i++) {
            int idx = tid + i * 128;
            int col = idx >> 5, kk = idx & 31;
            sW[kk * PW + col] = W[(size_t)col * ldw + woff + kb + kk];
        }
        __syncthreads();
#pragma unroll
        for (int kk = 0; kk < 32; kk++) {
            float4 a0 = *(const float4*)&sA[kk * PA + trow * 8];
            float4 a1 = *(const float4*)&sA[kk * PA + trow * 8 + 4];
            unsigned long long ap[4];
            PACK2(ap[0], a0.x, a0.y);
            PACK2(ap[1], a0.z, a0.w);
            PACK2(ap[2], a1.x, a1.y);
            PACK2(ap[3], a1.z, a1.w);
            float w[CT];
#pragma unroll
            for (int j = 0; j < CT; j += 4) {
                float4 wv = *(const float4*)&sW[kk * PW + tcol * CT + j];
                w[j] = wv.x; w[j + 1] = wv.y; w[j + 2] = wv.z; w[j + 3] = wv.w;
            }
            unsigned long long wd[CT];
#pragma unroll
            for (int j = 0; j < CT; j++) PACK2(wd[j], w[j], w[j]);
#pragma unroll
            for (int p = 0; p < 4; p++)
#pragma unroll
                for (int j = 0; j < CT; j++) FMA2(acc2[p][j], ap[p], wd[j]);
        }
    }
#pragma unroll
    for (int p = 0; p < 4; p++) {
        int gr0 = r0 + trow * 8 + 2 * p;
#pragma unroll
        for (int j = 0; j < CT; j++) {
            int col = tcol * CT + j;
            float b = bias ? bias[col] : 0.f;
            float lo, hi;
            UNPK2(lo, hi, acc2[p][j]);
            if (gr0 < nrows)     out[(size_t)gr0 * opitch + ocol + col]       = lo + b;
            if (gr0 + 1 < nrows) out[(size_t)(gr0 + 1) * opitch + ocol + col] = hi + b;
        }
    }
}

// ======================= GAT pieces ========================================

__global__ void attn_kernel(const float* __restrict__ h, const float* __restrict__ as,
                            const float* __restrict__ ad,
                            float* __restrict__ asrc, float* __restrict__ adst) {
    int tid = blockIdx.x * blockDim.x + threadIdx.x;
    if (tid >= NN * 8) return;
    int n = tid >> 3, hd = tid & 7;
    const float* hp = h + (size_t)n * 128 + hd * 16;
    const float* ap = as + hd * 16;
    const float* dp = ad + hd * 16;
    float s1 = 0.f, s2 = 0.f;
#pragma unroll
    for (int c = 0; c < 16; c++) {
        float v = hp[c];
        s1 = fmaf(v, ap[c], s1);
        s2 = fmaf(v, dp[c], s2);
    }
    asrc[tid] = s1;
    adst[tid] = s2;
}

// one warp per node, online softmax; lane owns 4 features, head = lane>>2
__global__ void gat_aggregate(const float* __restrict__ hfeat,
                              const float* __restrict__ asrc, const float* __restrict__ adst,
                              const int* __restrict__ off, const int* __restrict__ csr,
                              const float* __restrict__ bg, float* __restrict__ outp) {
    int gw = (blockIdx.x * blockDim.x + threadIdx.x) >> 5;
    if (gw >= NN) return;
    int lane = threadIdx.x & 31;
    int head = lane >> 2;
    float ad = adst[gw * 8 + head];
    float mm = -INFINITY, den = 0.f;
    float4 acc = make_float4(0.f, 0.f, 0.f, 0.f);
    int s0 = off[gw], s1 = off[gw + 1];
    for (int i = s0; i < s1; i++) {
        int s = csr[i];
        float e = asrc[s * 8 + head] + ad;
        e = (e >= 0.f) ? e : 0.2f * e;
        if (e > mm) {
            float sc = __expf(mm - e);
            den *= sc;
            acc.x *= sc; acc.y *= sc; acc.z *= sc; acc.w *= sc;
            mm = e;
        }
        float p = __expf(e - mm);
        den += p;
        float4 hv = *(const float4*)&hfeat[(size_t)s * 128 + lane * 4];
        acc.x = fmaf(hv.x, p, acc.x);
        acc.y = fmaf(hv.y, p, acc.y);
        acc.z = fmaf(hv.z, p, acc.z);
        acc.w = fmaf(hv.w, p, acc.w);
    }
    float inv = 1.f / (den + 1e-16f);
    float4 bgv = *(const float4*)&bg[lane * 4];
    acc.x = fmaf(acc.x, inv, bgv.x);
    acc.y = fmaf(acc.y, inv, bgv.y);
    acc.z = fmaf(acc.z, inv, bgv.z);
    acc.w = fmaf(acc.w, inv, bgv.w);
    *(float4*)&outp[(size_t)gw * 128 + lane * 4] = acc;
}

// ======================= BatchNorm =========================================

__global__ void zero_stats_kernel(float* sums, float* sq) {
    int f = threadIdx.x;
    if (f < 128) { sums[f] = 0.f; sq[f] = 0.f; }
}

__global__ void bn_sum_kernel(const float* __restrict__ x, float* __restrict__ sums,
                              int nrows, int F) {
    int f = threadIdx.x;
    float s = 0.f;
    for (int r = blockIdx.x; r < nrows; r += gridDim.x) s += x[(size_t)r * F + f];
    atomicAdd(&sums[f], s);
}

__global__ void bn_sqsum_kernel(const float* __restrict__ x, const float* __restrict__ mean,
                                float* __restrict__ sq, int nrows, int F) {
    int f = threadIdx.x;
    float mu = mean[f];
    float s = 0.f;
    for (int r = blockIdx.x; r < nrows; r += gridDim.x) {
        float d = x[(size_t)r * F + f] - mu;
        s = fmaf(d, d, s);
    }
    atomicAdd(&sq[f], s);
}

__global__ void bn_fin_mean_kernel(const float* sums, float* mean, int F, float invN) {
    int f = threadIdx.x;
    if (f < F) mean[f] = sums[f] * invN;
}

__global__ void bn_fin_rstd_kernel(const float* sq, float* rstd, int F, float invN) {
    int f = threadIdx.x;
    if (f < F) rstd[f] = rsqrtf(sq[f] * invN + 1e-5f);
}

// BN + ELU over (N,128)
__global__ void bn_elu_kernel(const float* __restrict__ x, const float* __restrict__ mean,
                              const float* __restrict__ rstd, const float* __restrict__ gamma,
                              const float* __restrict__ beta, float* __restrict__ out, int total) {
    int i = (blockIdx.x * blockDim.x + threadIdx.x) * 4;
    if (i >= total) return;
    float4 v = *(const float4*)&x[i];
    int f = i & 127;
    float r[4] = {v.x, v.y, v.z, v.w};
#pragma unroll
    for (int k = 0; k < 4; k++) {
        int ff = f + k;
        float t = (r[k] - mean[ff]) * rstd[ff] * gamma[ff] + beta[ff];
        r[k] = (t > 0.f) ? t : expm1f(t);
    }
    *(float4*)&out[i] = make_float4(r[0], r[1], r[2], r[3]);
}

// ======================= Edge scorer + gumbel gate =========================

__global__ void edge_logits_kernel(const float* __restrict__ prpc,
                                   const int* __restrict__ rowA, const int* __restrict__ colA,
                                   const float* __restrict__ gumbel,
                                   const float* __restrict__ bs1,
                                   const float* __restrict__ ws2,
                                   const float* __restrict__ bs2,
                                   float* __restrict__ wout, float* __restrict__ lrout) {
    __shared__ float sw2[64];
    __shared__ float sb1[64];
    if (threadIdx.x < 64) { sw2[threadIdx.x] = ws2[threadIdx.x]; sb1[threadIdx.x] = bs1[threadIdx.x]; }
    __syncthreads();
    int ge = (blockIdx.x * blockDim.x + threadIdx.x) >> 5;
    if (ge >= EE) return;
    int lane = threadIdx.x & 31;
    int r = rowA[ge];
    int c = colA[ge];
    float p0 = prpc[(size_t)r * 128 + lane]      + prpc[(size_t)c * 128 + 64 + lane] + sb1[lane];
    float p1 = prpc[(size_t)r * 128 + 32 + lane] + prpc[(size_t)c * 128 + 96 + lane] + sb1[32 + lane];
    p0 = fmaxf(p0, 0.f);
    p1 = fmaxf(p1, 0.f);
    float part = p0 * sw2[lane] + p1 * sw2[32 + lane];
#pragma unroll
    for (int d = 16; d; d >>= 1) part += __shfl_xor_sync(0xffffffffu, part, d);
    if (lane == 0) {
        float lr = part + bs2[0];
        lrout[ge] = lr;
        float g0 = gumbel[2 * (size_t)ge];
        float g1 = gumbel[2 * (size_t)ge + 1];
        wout[ge] = (lr + g1 > g0) ? 1.f : 0.f;
    }
}

// h_sparse = h_base + segment_sum(weights * h_base[col], row)
__global__ void sparse_agg_kernel(const float* __restrict__ hbase,
                                  const int* __restrict__ off2,
                                  const int* __restrict__ col, const int* __restrict__ eid,
                                  const float* __restrict__ w, float* __restrict__ outp) {
    int gw = (blockIdx.x * blockDim.x + threadIdx.x) >> 5;
    if (gw >= NN) return;
    int lane = threadIdx.x & 31;
    float4 acc = *(const float4*)&hbase[(size_t)gw * 128 + lane * 4];
    int s0 = off2[gw], s1 = off2[gw + 1];
    for (int i = s0; i < s1; i++) {
        int e = eid[i];
        if (w[e] != 0.f) {
            int c = col[i];
            float4 hv = *(const float4*)&hbase[(size_t)c * 128 + lane * 4];
            acc.x += hv.x; acc.y += hv.y; acc.z += hv.z; acc.w += hv.w;
        }
    }
    *(float4*)&outp[(size_t)gw * 128 + lane * 4] = acc;
}

// ======================= Classifier head ===================================

__global__ void __launch_bounds__(256)
classifier_kernel(const float* __restrict__ cpre, const float* __restrict__ mean,
                  const float* __restrict__ rstd, const float* __restrict__ gc,
                  const float* __restrict__ bec, const float* __restrict__ Wc2,
                  const float* __restrict__ bc2, float* __restrict__ outls) {
    __shared__ float sW[64 * 64];   // sW[f*64 + j], j>=40 zero
    __shared__ float sb[40];
    __shared__ float sc[8][64];
    for (int idx = threadIdx.x; idx < 64 * 64; idx += blockDim.x) {
        int f = idx >> 6, j = idx & 63;
        sW[idx] = (j < 40) ? Wc2[j * 64 + f] : 0.f;
    }
    if (threadIdx.x < 40) sb[threadIdx.x] = bc2[threadIdx.x];
    __syncthreads();
    int gw = (blockIdx.x * blockDim.x + threadIdx.x) >> 5;
    int lane = threadIdx.x & 31;
    int wib = threadIdx.x >> 5;
    if (gw >= NN) return;
    float v0 = cpre[(size_t)gw * 64 + lane];
    float v1 = cpre[(size_t)gw * 64 + 32 + lane];
    int f0 = lane, f1 = lane + 32;
    sc[wib][lane]      = fmaxf((v0 - mean[f0]) * rstd[f0] * gc[f0] + bec[f0], 0.f);
    sc[wib][lane + 32] = fmaxf((v1 - mean[f1]) * rstd[f1] * gc[f1] + bec[f1], 0.f);
    __syncwarp();
    float l0 = sb[lane];
    float l1 = (lane < 8) ? sb[lane + 32] : 0.f;
#pragma unroll
    for (int f = 0; f < 64; f++) {
        float cv = sc[wib][f];
        l0 = fmaf(cv, sW[f * 64 + lane], l0);
        l1 = fmaf(cv, sW[f * 64 + lane + 32], l1);
    }
    float mx = fmaxf(l0, (lane < 8) ? l1 : -INFINITY);
#pragma unroll
    for (int d = 16; d; d >>= 1) mx = fmaxf(mx, __shfl_xor_sync(0xffffffffu, mx, d));
    float s = expf(l0 - mx) + ((lane < 8) ? expf(l1 - mx) : 0.f);
#pragma unroll
    for (int d = 16; d; d >>= 1) s += __shfl_xor_sync(0xffffffffu, s, d);
    float lse = mx + logf(s);
    outls[(size_t)gw * 40 + lane] = l0 - lse;
    if (lane < 8) outls[(size_t)gw * 40 + 32 + lane] = l1 - lse;
}

// ======================= Host orchestration ================================

extern "C" void kernel_launch(void* const* d_in, const int* in_sizes, int n_in,
                              void* d_out, int out_size) {
    (void)in_sizes; (void)n_in; (void)out_size;

    float* S = nullptr;
    cudaGetSymbolAddress((void**)&S, g_scratch);

    float* bufA = S;                       // N*128
    float* bufH = S + 6400000;             // N*128
    float* bufG = S + 12800000;            // N*128
    float* bufC = S + 19200000;            // N*64
    float* asrc = S + 22400000;            // N*8
    float* adst = S + 22800000;
    float* sums = S + 24000000;
    float* sq   = sums + 128;
    float* mean = sums + 256;
    float* rstd = sums + 384;
    int* ip    = (int*)(S + 24000512);
    int* rowA  = ip;                       // EE
    int* colA  = rowA + EE;                // EE
    int* off1  = colA + EE;                // NN+1
    int* off2  = off1 + (NN + 1);          // NN+1
    int* cur1  = off2 + (NN + 1);
    int* cur2  = cur1 + NN;
    int* cnt1  = cur2 + NN;
    int* cnt2  = cnt1 + NN;
    int* csr1  = cnt2 + NN;                // EE + NN
    int* csr2c = csr1 + (EE + NN);         // EE
    int* csr2e = csr2c + EE;               // EE
    int* flag64 = csr2e + EE;              // 1
    int* btot   = flag64 + 1;              // 2*(NTILE+1)

    const float* x      = (const float*)d_in[0];
    const int*   eiw    = (const int*)d_in[1];
    const float* gumbel = (const float*)d_in[2];
    const float* W_res  = (const float*)d_in[3];
    const float* b_res  = (const float*)d_in[4];
    const float* Wg1    = (const float*)d_in[5];
    const float* as1    = (const float*)d_in[6];
    const float* ad1    = (const float*)d_in[7];
    const float* bg1    = (const float*)d_in[8];
    const float* g1     = (const float*)d_in[9];
    const float* be1    = (const float*)d_in[10];
    const float* Wg2    = (const float*)d_in[11];
    const float* as2    = (const float*)d_in[12];
    const float* ad2    = (const float*)d_in[13];
    const float* bg2    = (const float*)d_in[14];
    const float* g2     = (const float*)d_in[15];
    const float* be2    = (const float*)d_in[16];
    const float* Ws1    = (const float*)d_in[17];
    const float* bs1    = (const float*)d_in[18];
    const float* Ws2    = (const float*)d_in[19];
    const float* bs2    = (const float*)d_in[20];
    const float* Wc1    = (const float*)d_in[21];
    const float* bc1    = (const float*)d_in[22];
    const float* gc     = (const float*)d_in[23];
    const float* bec    = (const float*)d_in[24];
    const float* Wc2    = (const float*)d_in[25];
    const float* bc2    = (const float*)d_in[26];

    float* out_ls = (float*)d_out;                    // N*40
    float* out_w  = out_ls + (size_t)NN * OUTC;       // E
    float* out_lr = out_w + EE;                       // E

    const int NB   = (NN + 255) / 256;
    const int EB   = (EE + 255) / 256;
    const int NHB  = (NN * 8 + 255) / 256;
    const int WRPN = (NN * 32) / 256;
    const int WRPE = (EE * 32) / 256;
    const int GEMG = (NN + 63) / 64;
    const float invN = 1.f / (float)NN;

    // ---- edge_index dtype probe + convert ----
    init_counts_kernel<<<NB, 256>>>(cnt1, cnt2, flag64);
    detect_kernel<<<256, 256>>>(eiw, flag64);
    convert_kernel<<<EB, 256>>>(eiw, flag64, rowA, colA);

    // ---- CSR build (parallel scan) ----
    hist_kernel<<<EB, 256>>>(rowA, colA, cnt1, cnt2);
    scan_p1<<<dim3(NTILE, 2), 256>>>(cnt1, cnt2, btot);
    scan_p2<<<dim3(1, 2), 256>>>(btot);
    scan_p3<<<dim3(NTILE, 2), 256>>>(cnt1, cnt2, btot, off1, off2);
    init_cursors_kernel<<<NB, 256>>>(off1, off2, cur1, cur2, csr1);
    fill_kernel<<<EB, 256>>>(rowA, colA, cur1, csr1, cur2, csr2c, csr2e);

    // ---- x_proj ----
    gemm_k128<128><<<GEMG, 128>>>(x, W_res, 128, 0, b_res, bufA, 128, 0, NN);

    // ---- GAT layer 1 ----
    gemm_k128<128><<<GEMG, 128>>>(bufA, Wg1, 128, 0, nullptr, bufH, 128, 0, NN);
    attn_kernel<<<NHB, 256>>>(bufH, as1, ad1, asrc, adst);
    gat_aggregate<<<WRPN, 256>>>(bufH, asrc, adst, off1, csr1, bg1, bufG);
    zero_stats_kernel<<<1, 128>>>(sums, sq);
    bn_sum_kernel<<<512, 128>>>(bufG, sums, NN, 128);
    bn_fin_mean_kernel<<<1, 128>>>(sums, mean, 128, invN);
    bn_sqsum_kernel<<<512, 128>>>(bufG, mean, sq, NN, 128);
    bn_fin_rstd_kernel<<<1, 128>>>(sq, rstd, 128, invN);
    bn_elu_kernel<<<(NN * 32 + 255) / 256, 256>>>(bufG, mean, rstd, g1, be1, bufA, NN * 128);

    // ---- GAT layer 2 ----
    gemm_k128<128><<<GEMG, 128>>>(bufA, Wg2, 128, 0, nullptr, bufH, 128, 0, NN);
    attn_kernel<<<NHB, 256>>>(bufH, as2, ad2, asrc, adst);
    gat_aggregate<<<WRPN, 256>>>(bufH, asrc, adst, off1, csr1, bg2, bufG);
    zero_stats_kernel<<<1, 128>>>(sums, sq);
    bn_sum_kernel<<<512, 128>>>(bufG, sums, NN, 128);
    bn_fin_mean_kernel<<<1, 128>>>(sums, mean, 128, invN);
    bn_sqsum_kernel<<<512, 128>>>(bufG, mean, sq, NN, 128);
    bn_fin_rstd_kernel<<<1, 128>>>(sq, rstd, 128, invN);
    bn_elu_kernel<<<(NN * 32 + 255) / 256, 256>>>(bufG, mean, rstd, g2, be2, bufA, NN * 128);
    // bufA = h_base

    // ---- edge scorer ----
    gemm_k128<64><<<GEMG, 128>>>(bufA, Ws1, 256, 0,   nullptr, bufH, 128, 0,  NN);
    gemm_k128<64><<<GEMG, 128>>>(bufA, Ws1, 256, 128, nullptr, bufH, 128, 64, NN);
    edge_logits_kernel<<<WRPE, 256>>>(bufH, rowA, colA, gumbel, bs1, Ws2, bs2, out_w, out_lr);

    // ---- sparse aggregation ----
    sparse_agg_kernel<<<WRPN, 256>>>(bufA, off2, csr2c, csr2e, out_w, bufG);

    // ---- classifier ----
    gemm_k128<64><<<GEMG, 128>>>(bufG, Wc1, 128, 0, bc1, bufC, 64, 0, NN);
    zero_stats_kernel<<<1, 128>>>(sums, sq);
    bn_sum_kernel<<<512, 64>>>(bufC, sums, NN, 64);
    bn_fin_mean_kernel<<<1, 64>>>(sums, mean, 64, invN);
    bn_sqsum_kernel<<<512, 64>>>(bufC, mean, sq, NN, 64);
    bn_fin_rstd_kernel<<<1, 64>>>(sq, rstd, 64, invN);
    classifier_kernel<<<WRPN, 256>>>(bufC, mean, rstd, gc, bec, Wc2, bc2, out_ls);
}

// round 6
// speedup vs baseline: 1.2364x; 1.1181x over previous
#include <cuda_runtime.h>
#include <cuda_bf16.h>
#include <math.h>

#define NN 50000
#define EE 800000
#define OUTC 40
#define NTILE 196            // ceil(50000/256)

__device__ __align__(128) float g_scratch[29000000];

#define PACK2(dst, lo, hi) asm("mov.b64 %0, {%1, %2};" : "=l"(dst) : "f"(lo), "f"(hi))
#define UNPK2(lo, hi, v)   asm("mov.b64 {%0, %1}, %2;" : "=f"(lo), "=f"(hi) : "l"(v))
#define FMA2(acc, a, b)    asm("fma.rn.f32x2 %0, %1, %2, %0;" : "+l"(acc) : "l"(a), "l"(b))

// ======================= init: counts, flag, float stat accumulators =======
__global__ void init_kernel(int* c1, int* c2, int* flag64, float* statz) {
    int i = blockIdx.x * blockDim.x + threadIdx.x;
    if (i < NN) { c1[i] = 1; c2[i] = 0; }     // c1 starts at 1 (self-loop)
    if (i == 0) *flag64 = 1;
    if (i < 640) statz[i] = 0.f;
}

__global__ void detect_kernel(const int* __restrict__ w, int* flag64) {
    int any = 0;
    for (int i = blockIdx.x * blockDim.x + threadIdx.x; i < EE; i += gridDim.x * blockDim.x)
        any |= w[2 * i + 1];
    if (any) atomicAnd(flag64, 0);
}

// convert edge_index to int32 row/col AND histogram in one pass
__global__ void convert_hist_kernel(const int* __restrict__ w, const int* __restrict__ flag64,
                                    int* __restrict__ rowA, int* __restrict__ colA,
                                    int* c1, int* c2) {
    int e = blockIdx.x * blockDim.x + threadIdx.x;
    if (e >= EE) return;
    int r, c;
    if (*flag64) { r = w[2 * e]; c = w[2 * (EE + e)]; }
    else         { r = w[e];     c = w[EE + e]; }
    rowA[e] = r; colA[e] = c;
    atomicAdd(&c1[c], 1);
    atomicAdd(&c2[r], 1);
}

// ---- parallel 3-phase exclusive scan over two arrays (gridDim.y selects) ----
__global__ void scan_p1(const int* __restrict__ cnt1, const int* __restrict__ cnt2,
                        int* __restrict__ btot) {
    const int* cnt = blockIdx.y ? cnt2 : cnt1;
    __shared__ int sw[8];
    int idx = blockIdx.x * 256 + threadIdx.x;
    int v = (idx < NN) ? cnt[idx] : 0;
#pragma unroll
    for (int d = 16; d; d >>= 1) v += __shfl_xor_sync(0xffffffffu, v, d);
    if ((threadIdx.x & 31) == 0) sw[threadIdx.x >> 5] = v;
    __syncthreads();
    if (threadIdx.x == 0) {
        int s = 0;
#pragma unroll
        for (int i = 0; i < 8; i++) s += sw[i];
        btot[blockIdx.y * (NTILE + 1) + blockIdx.x] = s;
    }
}

__global__ void scan_p2(int* __restrict__ btot) {
    int* b = btot + blockIdx.y * (NTILE + 1);
    __shared__ int sw[8], sw2[9];
    int t = threadIdx.x, lane = t & 31, wid = t >> 5;
    int v = (t < NTILE) ? b[t] : 0;
    int inc = v;
#pragma unroll
    for (int d = 1; d < 32; d <<= 1) { int y = __shfl_up_sync(0xffffffffu, inc, d); if (lane >= d) inc += y; }
    if (lane == 31) sw[wid] = inc;
    __syncthreads();
    if (t == 0) { sw2[0] = 0; for (int i = 0; i < 8; i++) sw2[i + 1] = sw2[i] + sw[i]; }
    __syncthreads();
    int excl = sw2[wid] + inc - v;
    if (t < NTILE) b[t] = excl;
    if (t == 0) b[NTILE] = sw2[8];
}

// scan phase 3 + cursor init + self-loop placement
__global__ void scan_p3(const int* __restrict__ cnt1, const int* __restrict__ cnt2,
                        const int* __restrict__ btot,
                        int* __restrict__ off1, int* __restrict__ off2,
                        int* __restrict__ cur1, int* __restrict__ cur2, int* __restrict__ csr1) {
    const int* cnt = blockIdx.y ? cnt2 : cnt1;
    int* off = blockIdx.y ? off2 : off1;
    const int* b = btot + blockIdx.y * (NTILE + 1);
    __shared__ int sw[8], sw2[9];
    int t = threadIdx.x, lane = t & 31, wid = t >> 5;
    int idx = blockIdx.x * 256 + t;
    int v = (idx < NN) ? cnt[idx] : 0;
    int inc = v;
#pragma unroll
    for (int d = 1; d < 32; d <<= 1) { int y = __shfl_up_sync(0xffffffffu, inc, d); if (lane >= d) inc += y; }
    if (lane == 31) sw[wid] = inc;
    __syncthreads();
    if (t == 0) { sw2[0] = 0; for (int i = 0; i < 8; i++) sw2[i + 1] = sw2[i] + sw[i]; }
    __syncthreads();
    int excl = b[blockIdx.x] + sw2[wid] + inc - v;
    if (idx < NN) {
        off[idx] = excl;
        if (blockIdx.y == 0) { cur1[idx] = excl + 1; csr1[excl] = idx; }
        else                 cur2[idx] = excl;
    }
    if (blockIdx.x == 0 && t == 0) off[NN] = b[NTILE];
}

__global__ void fill_kernel(const int* __restrict__ rowA, const int* __restrict__ colA,
                            int* cur1, int* csr1,
                            int* cur2, int* csr2c, int* csr2e) {
    int e = blockIdx.x * blockDim.x + threadIdx.x;
    if (e >= EE) return;
    int r = rowA[e];
    int c = colA[e];
    int p = atomicAdd(&cur1[c], 1);
    csr1[p] = r;
    int q = atomicAdd(&cur2[r], 1);
    csr2c[q] = c;
    csr2e[q] = e;
}

// ======================= GEMM (K = 128 fixed, f32x2 FMA) ====================
// out[n][ocol+col] = sum_k A'[n][k] * W[col*ldw + woff + k] + bias[col]
// A' = BN+ELU(A) when BNIN. ATTN: also emit per-head attention dots.
// STATS: accumulate per-col sum / sumsq into float globals.

template <int TC, bool BNIN, bool ATTN, bool STATS>
__global__ void __launch_bounds__(128)
gemm_k128(const float* __restrict__ A, const float* __restrict__ W,
          int ldw, int woff, const float* __restrict__ bias,
          float* __restrict__ out, int opitch, int ocol, int nrows,
          const float* __restrict__ bnm, const float* __restrict__ bnr,
          const float* __restrict__ bng, const float* __restrict__ bnb,
          const float* __restrict__ as, const float* __restrict__ ad,
          float* __restrict__ asrc, float* __restrict__ adst,
          float* gsum, float* gsq) {
    constexpr int CT = TC / 16;
    constexpr int PA = 68;
    constexpr int PW = TC + 4;
    __shared__ float sA[32 * PA];
    __shared__ float sW[32 * PW];
    const int tid = threadIdx.x;
    const int trow = tid >> 4;     // 0..7
    const int tcol = tid & 15;     // 0..15
    const int r0 = blockIdx.x * 64;

    unsigned long long acc2[4][CT];   // row-pairs x cols
#pragma unroll
    for (int p = 0; p < 4; p++)
#pragma unroll
        for (int j = 0; j < CT; j++) acc2[p][j] = 0ull;

    for (int kb = 0; kb < 128; kb += 32) {
        float bm = 0.f, br = 0.f, bgm = 0.f, bbt = 0.f;
        if (BNIN) {
            int kf = kb + (tid & 31);
            bm = bnm[kf]; br = bnr[kf]; bgm = bng[kf]; bbt = bnb[kf];
        }
        __syncthreads();
#pragma unroll
        for (int i = 0; i < 16; i++) {
            int idx = tid + i * 128;
            int row = idx >> 5, kk = idx & 31;
            int gr = r0 + row;
            float v = (gr < nrows) ? A[(size_t)gr * 128 + kb + kk] : 0.f;
            if (BNIN && gr < nrows) {
                float t = (v - bm) * br * bgm + bbt;
                v = (t > 0.f) ? t : expm1f(t);
            }
            sA[kk * PA + row] = v;
        }
#pragma unroll
        for (int i = 0; i < (TC * 32) / 128; i++) {
            int idx = tid + i * 128;
            int col = idx >> 5, kk = idx & 31;
            sW[kk * PW + col] = W[(size_t)col * ldw + woff + kb + kk];
        }
        __syncthreads();
#pragma unroll
        for (int kk = 0; kk < 32; kk++) {
            float4 a0 = *(const float4*)&sA[kk * PA + trow * 8];
            float4 a1 = *(const float4*)&sA[kk * PA + trow * 8 + 4];
            unsigned long long ap[4];
            PACK2(ap[0], a0.x, a0.y);
            PACK2(ap[1], a0.z, a0.w);
            PACK2(ap[2], a1.x, a1.y);
            PACK2(ap[3], a1.z, a1.w);
            float w[CT];
#pragma unroll
            for (int j = 0; j < CT; j += 4) {
                float4 wv = *(const float4*)&sW[kk * PW + tcol * CT + j];
                w[j] = wv.x; w[j + 1] = wv.y; w[j + 2] = wv.z; w[j + 3] = wv.w;
            }
            unsigned long long wd[CT];
#pragma unroll
            for (int j = 0; j < CT; j++) PACK2(wd[j], w[j], w[j]);
#pragma unroll
            for (int p = 0; p < 4; p++)
#pragma unroll
                for (int j = 0; j < CT; j++) FMA2(acc2[p][j], ap[p], wd[j]);
        }
    }
    // ---- store ----
#pragma unroll
    for (int p = 0; p < 4; p++) {
        int gr0 = r0 + trow * 8 + 2 * p;
#pragma unroll
        for (int j = 0; j < CT; j++) {
            int col = tcol * CT + j;
            float b = bias ? bias[col] : 0.f;
            float lo, hi;
            UNPK2(lo, hi, acc2[p][j]);
            if (gr0 < nrows)     out[(size_t)gr0 * opitch + ocol + col]       = lo + b;
            if (gr0 + 1 < nrows) out[(size_t)(gr0 + 1) * opitch + ocol + col] = hi + b;
        }
    }
    // ---- fused attention dots (TC=128 only): a_src/a_dst per (row, head) ----
    if (ATTN) {
#pragma unroll
        for (int p = 0; p < 4; p++) {
            float s1lo = 0.f, s2lo = 0.f, s1hi = 0.f, s2hi = 0.f;
#pragma unroll
            for (int j = 0; j < CT; j++) {
                int col = tcol * CT + j;
                float aS = __ldg(&as[col]), aD = __ldg(&ad[col]);
                float lo, hi;
                UNPK2(lo, hi, acc2[p][j]);
                s1lo = fmaf(lo, aS, s1lo); s2lo = fmaf(lo, aD, s2lo);
                s1hi = fmaf(hi, aS, s1hi); s2hi = fmaf(hi, aD, s2hi);
            }
            s1lo += __shfl_xor_sync(0xffffffffu, s1lo, 1);
            s2lo += __shfl_xor_sync(0xffffffffu, s2lo, 1);
            s1hi += __shfl_xor_sync(0xffffffffu, s1hi, 1);
            s2hi += __shfl_xor_sync(0xffffffffu, s2hi, 1);
            if (!(tcol & 1)) {
                int h = tcol >> 1;
                int rlo = r0 + trow * 8 + 2 * p;
                if (rlo < nrows)     { asrc[rlo * 8 + h] = s1lo;       adst[rlo * 8 + h] = s2lo; }
                if (rlo + 1 < nrows) { asrc[(rlo + 1) * 8 + h] = s1hi; adst[(rlo + 1) * 8 + h] = s2hi; }
            }
        }
    }
    // ---- fused per-feature BN statistics ----
    if (STATS) {
        __shared__ float s_s[8][TC], s_q[8][TC];
#pragma unroll
        for (int j = 0; j < CT; j++) {
            int col = tcol * CT + j;
            float b = bias ? bias[col] : 0.f;
            float ps = 0.f, pq = 0.f;
#pragma unroll
            for (int p = 0; p < 4; p++) {
                int gr0 = r0 + trow * 8 + 2 * p;
                float lo, hi;
                UNPK2(lo, hi, acc2[p][j]);
                if (gr0 < nrows)     { float v = lo + b; ps += v; pq = fmaf(v, v, pq); }
                if (gr0 + 1 < nrows) { float v = hi + b; ps += v; pq = fmaf(v, v, pq); }
            }
            s_s[trow][col] = ps;
            s_q[trow][col] = pq;
        }
        __syncthreads();
        if (tid < TC) {
            float S = 0.f, Q = 0.f;
#pragma unroll
            for (int w = 0; w < 8; w++) { S += s_s[w][tid]; Q += s_q[w][tid]; }
            atomicAdd(&gsum[tid], S);
            atomicAdd(&gsq[tid],  Q);
        }
    }
}

// ======================= GAT aggregation (online softmax + BN stats) =======
// one warp per node; lane owns 4 features, head = lane>>2

__global__ void __launch_bounds__(256)
gat_aggregate(const float* __restrict__ hfeat,
              const float* __restrict__ asrc, const float* __restrict__ adst,
              const int* __restrict__ off, const int* __restrict__ csr,
              const float* __restrict__ bg, float* __restrict__ outp,
              float* gsum, float* gsq) {
    __shared__ float s_v[8][128];
    int gw = (blockIdx.x * blockDim.x + threadIdx.x) >> 5;
    int lane = threadIdx.x & 31;
    int wib = threadIdx.x >> 5;
    int head = lane >> 2;
    float ad = adst[gw * 8 + head];
    float mm = -INFINITY, den = 0.f;
    float4 acc = make_float4(0.f, 0.f, 0.f, 0.f);
    int s0 = off[gw], s1 = off[gw + 1];
    for (int i = s0; i < s1; i++) {
        int s = csr[i];
        float e = asrc[s * 8 + head] + ad;
        e = (e >= 0.f) ? e : 0.2f * e;
        if (e > mm) {
            float sc = __expf(mm - e);
            den *= sc;
            acc.x *= sc; acc.y *= sc; acc.z *= sc; acc.w *= sc;
            mm = e;
        }
        float p = __expf(e - mm);
        den += p;
        float4 hv = *(const float4*)&hfeat[(size_t)s * 128 + lane * 4];
        acc.x = fmaf(hv.x, p, acc.x);
        acc.y = fmaf(hv.y, p, acc.y);
        acc.z = fmaf(hv.z, p, acc.z);
        acc.w = fmaf(hv.w, p, acc.w);
    }
    float inv = 1.f / (den + 1e-16f);
    float4 bgv = *(const float4*)&bg[lane * 4];
    acc.x = fmaf(acc.x, inv, bgv.x);
    acc.y = fmaf(acc.y, inv, bgv.y);
    acc.z = fmaf(acc.z, inv, bgv.z);
    acc.w = fmaf(acc.w, inv, bgv.w);
    *(float4*)&outp[(size_t)gw * 128 + lane * 4] = acc;
    // per-block BN stats
    *(float4*)&s_v[wib][lane * 4] = acc;
    __syncthreads();
    int t = threadIdx.x;
    if (t < 128) {
        float S = 0.f, Q = 0.f;
#pragma unroll
        for (int w = 0; w < 8; w++) { float v = s_v[w][t]; S += v; Q = fmaf(v, v, Q); }
        atomicAdd(&gsum[t], S);
        atomicAdd(&gsq[t],  Q);
    }
}

// ======================= BN finalize + BN-ELU ==============================

__global__ void bn_finalize(const float* __restrict__ gs, const float* __restrict__ gq,
                            float* mean, float* rstd, int F) {
    int f = threadIdx.x;
    if (f < F) {
        double invN = 1.0 / (double)NN;
        double mu = (double)gs[f] * invN;
        double var = (double)gq[f] * invN - mu * mu;
        if (var < 0.0) var = 0.0;
        mean[f] = (float)mu;
        rstd[f] = rsqrtf((float)var + 1e-5f);
    }
}

__global__ void bn_elu_kernel(const float* __restrict__ x, const float* __restrict__ mean,
                              const float* __restrict__ rstd, const float* __restrict__ gamma,
                              const float* __restrict__ beta, float* __restrict__ out, int total) {
    int i = (blockIdx.x * blockDim.x + threadIdx.x) * 4;
    if (i >= total) return;
    float4 v = *(const float4*)&x[i];
    int f = i & 127;
    float r[4] = {v.x, v.y, v.z, v.w};
#pragma unroll
    for (int k = 0; k < 4; k++) {
        int ff = f + k;
        float t = (r[k] - mean[ff]) * rstd[ff] * gamma[ff] + beta[ff];
        r[k] = (t > 0.f) ? t : expm1f(t);
    }
    *(float4*)&out[i] = make_float4(r[0], r[1], r[2], r[3]);
}

// ======================= Edge scorer + gumbel gate =========================

__global__ void edge_logits_kernel(const float* __restrict__ prpc,
                                   const int* __restrict__ rowA, const int* __restrict__ colA,
                                   const float* __restrict__ gumbel,
                                   const float* __restrict__ bs1,
                                   const float* __restrict__ ws2,
                                   const float* __restrict__ bs2,
                                   float* __restrict__ wout, float* __restrict__ lrout) {
    __shared__ float sw2[64];
    __shared__ float sb1[64];
    if (threadIdx.x < 64) { sw2[threadIdx.x] = ws2[threadIdx.x]; sb1[threadIdx.x] = bs1[threadIdx.x]; }
    __syncthreads();
    int ge = (blockIdx.x * blockDim.x + threadIdx.x) >> 5;
    if (ge >= EE) return;
    int lane = threadIdx.x & 31;
    int r = rowA[ge];
    int c = colA[ge];
    float p0 = prpc[(size_t)r * 128 + lane]      + prpc[(size_t)c * 128 + 64 + lane] + sb1[lane];
    float p1 = prpc[(size_t)r * 128 + 32 + lane] + prpc[(size_t)c * 128 + 96 + lane] + sb1[32 + lane];
    p0 = fmaxf(p0, 0.f);
    p1 = fmaxf(p1, 0.f);
    float part = p0 * sw2[lane] + p1 * sw2[32 + lane];
#pragma unroll
    for (int d = 16; d; d >>= 1) part += __shfl_xor_sync(0xffffffffu, part, d);
    if (lane == 0) {
        float lr = part + bs2[0];
        lrout[ge] = lr;
        float g0 = gumbel[2 * (size_t)ge];
        float g1 = gumbel[2 * (size_t)ge + 1];
        wout[ge] = (lr + g1 > g0) ? 1.f : 0.f;
    }
}

// h_sparse = h_base + segment_sum(weights * h_base[col], row)
__global__ void sparse_agg_kernel(const float* __restrict__ hbase,
                                  const int* __restrict__ off2,
                                  const int* __restrict__ col, const int* __restrict__ eid,
                                  const float* __restrict__ w, float* __restrict__ outp) {
    int gw = (blockIdx.x * blockDim.x + threadIdx.x) >> 5;
    if (gw >= NN) return;
    int lane = threadIdx.x & 31;
    float4 acc = *(const float4*)&hbase[(size_t)gw * 128 + lane * 4];
    int s0 = off2[gw], s1 = off2[gw + 1];
    for (int i = s0; i < s1; i++) {
        int e = eid[i];
        if (w[e] != 0.f) {
            int c = col[i];
            float4 hv = *(const float4*)&hbase[(size_t)c * 128 + lane * 4];
            acc.x += hv.x; acc.y += hv.y; acc.z += hv.z; acc.w += hv.w;
        }
    }
    *(float4*)&outp[(size_t)gw * 128 + lane * 4] = acc;
}

// ======================= Classifier head ===================================

__global__ void __launch_bounds__(256)
classifier_kernel(const float* __restrict__ cpre, const float* __restrict__ mean,
                  const float* __restrict__ rstd, const float* __restrict__ gc,
                  const float* __restrict__ bec, const float* __restrict__ Wc2,
                  const float* __restrict__ bc2, float* __restrict__ outls) {
    __shared__ float sW[64 * 64];   // sW[f*64 + j], j>=40 zero
    __shared__ float sb[40];
    __shared__ float sc[8][64];
    for (int idx = threadIdx.x; idx < 64 * 64; idx += blockDim.x) {
        int f = idx >> 6, j = idx & 63;
        sW[idx] = (j < 40) ? Wc2[j * 64 + f] : 0.f;
    }
    if (threadIdx.x < 40) sb[threadIdx.x] = bc2[threadIdx.x];
    __syncthreads();
    int gw = (blockIdx.x * blockDim.x + threadIdx.x) >> 5;
    int lane = threadIdx.x & 31;
    int wib = threadIdx.x >> 5;
    if (gw >= NN) return;
    float v0 = cpre[(size_t)gw * 64 + lane];
    float v1 = cpre[(size_t)gw * 64 + 32 + lane];
    int f0 = lane, f1 = lane + 32;
    sc[wib][lane]      = fmaxf((v0 - mean[f0]) * rstd[f0] * gc[f0] + bec[f0], 0.f);
    sc[wib][lane + 32] = fmaxf((v1 - mean[f1]) * rstd[f1] * gc[f1] + bec[f1], 0.f);
    __syncwarp();
    float l0 = sb[lane];
    float l1 = (lane < 8) ? sb[lane + 32] : 0.f;
#pragma unroll
    for (int f = 0; f < 64; f++) {
        float cv = sc[wib][f];
        l0 = fmaf(cv, sW[f * 64 + lane], l0);
        l1 = fmaf(cv, sW[f * 64 + lane + 32], l1);
    }
    float mx = fmaxf(l0, (lane < 8) ? l1 : -INFINITY);
#pragma unroll
    for (int d = 16; d; d >>= 1) mx = fmaxf(mx, __shfl_xor_sync(0xffffffffu, mx, d));
    float s = expf(l0 - mx) + ((lane < 8) ? expf(l1 - mx) : 0.f);
#pragma unroll
    for (int d = 16; d; d >>= 1) s += __shfl_xor_sync(0xffffffffu, s, d);
    float lse = mx + logf(s);
    outls[(size_t)gw * 40 + lane] = l0 - lse;
    if (lane < 8) outls[(size_t)gw * 40 + 32 + lane] = l1 - lse;
}

// ======================= Host orchestration ================================

extern "C" void kernel_launch(void* const* d_in, const int* in_sizes, int n_in,
                              void* d_out, int out_size) {
    (void)in_sizes; (void)n_in; (void)out_size;

    float* S = nullptr;
    cudaGetSymbolAddress((void**)&S, g_scratch);

    float* bufA = S;                       // N*128
    float* bufH = S + 6400000;             // N*128
    float* bufG = S + 12800000;            // N*128
    float* bufC = S + 19200000;            // N*64
    float* asrc = S + 22400000;            // N*8
    float* adst = S + 22800000;
    float* fpar = S + 23200000;            // BN mean/rstd params
    float* mean1 = fpar,       * rstd1 = fpar + 128;
    float* mean2 = fpar + 256, * rstd2 = fpar + 384;
    float* meanc = fpar + 512, * rstdc = fpar + 640;
    float* stat  = S + 23201024;           // float stat accumulators (640)
    float* s1s = stat,       * s1q = stat + 128;
    float* s2s = stat + 256, * s2q = stat + 384;
    float* scs = stat + 512, * scq = stat + 576;
    int* ip    = (int*)(S + 24000000);
    int* rowA  = ip;                       // EE
    int* colA  = rowA + EE;                // EE
    int* off1  = colA + EE;                // NN+1
    int* off2  = off1 + (NN + 1);          // NN+1
    int* cur1  = off2 + (NN + 1);
    int* cur2  = cur1 + NN;
    int* cnt1  = cur2 + NN;
    int* cnt2  = cnt1 + NN;
    int* csr1  = cnt2 + NN;                // EE + NN
    int* csr2c = csr1 + (EE + NN);         // EE
    int* csr2e = csr2c + EE;               // EE  (ends ~28,350,002)
    int* flag64 = csr2e + EE;              // 1
    int* btot   = flag64 + 1;              // 2*(NTILE+1) (ends ~28,350,397 < 29,000,000)

    const float* x      = (const float*)d_in[0];
    const int*   eiw    = (const int*)d_in[1];
    const float* gumbel = (const float*)d_in[2];
    const float* W_res  = (const float*)d_in[3];
    const float* b_res  = (const float*)d_in[4];
    const float* Wg1    = (const float*)d_in[5];
    const float* as1    = (const float*)d_in[6];
    const float* ad1    = (const float*)d_in[7];
    const float* bg1    = (const float*)d_in[8];
    const float* g1     = (const float*)d_in[9];
    const float* be1    = (const float*)d_in[10];
    const float* Wg2    = (const float*)d_in[11];
    const float* as2    = (const float*)d_in[12];
    const float* ad2    = (const float*)d_in[13];
    const float* bg2    = (const float*)d_in[14];
    const float* g2     = (const float*)d_in[15];
    const float* be2    = (const float*)d_in[16];
    const float* Ws1    = (const float*)d_in[17];
    const float* bs1    = (const float*)d_in[18];
    const float* Ws2    = (const float*)d_in[19];
    const float* bs2    = (const float*)d_in[20];
    const float* Wc1    = (const float*)d_in[21];
    const float* bc1    = (const float*)d_in[22];
    const float* gc     = (const float*)d_in[23];
    const float* bec    = (const float*)d_in[24];
    const float* Wc2    = (const float*)d_in[25];
    const float* bc2    = (const float*)d_in[26];

    float* out_ls = (float*)d_out;                    // N*40
    float* out_w  = out_ls + (size_t)NN * OUTC;       // E
    float* out_lr = out_w + EE;                       // E

    const int NB   = (NN + 255) / 256;
    const int EB   = (EE + 255) / 256;
    const int WRPN = (NN * 32) / 256;
    const int WRPE = (EE * 32) / 256;
    const int GEMG = (NN + 63) / 64;

    // 1..3: CSR front half + dtype probe
    init_kernel<<<NB, 256>>>(cnt1, cnt2, flag64, stat);
    detect_kernel<<<256, 256>>>(eiw, flag64);
    convert_hist_kernel<<<EB, 256>>>(eiw, flag64, rowA, colA, cnt1, cnt2);

    // 4: x_proj  (profile slot)
    gemm_k128<128, false, false, false><<<GEMG, 128>>>(
        x, W_res, 128, 0, b_res, bufA, 128, 0, NN,
        nullptr, nullptr, nullptr, nullptr, nullptr, nullptr, nullptr, nullptr, nullptr, nullptr);

    // 5..8: finish CSR
    scan_p1<<<dim3(NTILE, 2), 256>>>(cnt1, cnt2, btot);
    scan_p2<<<dim3(1, 2), 256>>>(btot);
    scan_p3<<<dim3(NTILE, 2), 256>>>(cnt1, cnt2, btot, off1, off2, cur1, cur2, csr1);
    fill_kernel<<<EB, 256>>>(rowA, colA, cur1, csr1, cur2, csr2c, csr2e);

    // 9..11: GAT layer 1
    gemm_k128<128, false, true, false><<<GEMG, 128>>>(
        bufA, Wg1, 128, 0, nullptr, bufH, 128, 0, NN,
        nullptr, nullptr, nullptr, nullptr, as1, ad1, asrc, adst, nullptr, nullptr);
    gat_aggregate<<<WRPN, 256>>>(bufH, asrc, adst, off1, csr1, bg1, bufG, s1s, s1q);
    bn_finalize<<<1, 128>>>(s1s, s1q, mean1, rstd1, 128);

    // 12..15: GAT layer 2 (BN+ELU of layer1 fused into A-load)
    gemm_k128<128, true, true, false><<<GEMG, 128>>>(
        bufG, Wg2, 128, 0, nullptr, bufH, 128, 0, NN,
        mean1, rstd1, g1, be1, as2, ad2, asrc, adst, nullptr, nullptr);
    gat_aggregate<<<WRPN, 256>>>(bufH, asrc, adst, off1, csr1, bg2, bufG, s2s, s2q);
    bn_finalize<<<1, 128>>>(s2s, s2q, mean2, rstd2, 128);
    bn_elu_kernel<<<(NN * 32 + 255) / 256, 256>>>(bufG, mean2, rstd2, g2, be2, bufA, NN * 128);
    // bufA = h_base

    // 16..18: edge scorer
    gemm_k128<64, false, false, false><<<GEMG, 128>>>(
        bufA, Ws1, 256, 0, nullptr, bufH, 128, 0, NN,
        nullptr, nullptr, nullptr, nullptr, nullptr, nullptr, nullptr, nullptr, nullptr, nullptr);
    gemm_k128<64, false, false, false><<<GEMG, 128>>>(
        bufA, Ws1, 256, 128, nullptr, bufH, 128, 64, NN,
        nullptr, nullptr, nullptr, nullptr, nullptr, nullptr, nullptr, nullptr, nullptr, nullptr);
    edge_logits_kernel<<<WRPE, 256>>>(bufH, rowA, colA, gumbel, bs1, Ws2, bs2, out_w, out_lr);

    // 19: sparse aggregation
    sparse_agg_kernel<<<WRPN, 256>>>(bufA, off2, csr2c, csr2e, out_w, bufG);

    // 20..22: classifier (BN stats fused into GEMM)
    gemm_k128<64, false, false, true><<<GEMG, 128>>>(
        bufG, Wc1, 128, 0, bc1, bufC, 64, 0, NN,
        nullptr, nullptr, nullptr, nullptr, nullptr, nullptr, nullptr, nullptr, scs, scq);
    bn_finalize<<<1, 64>>>(scs, scq, meanc, rstdc, 64);
    classifier_kernel<<<WRPN, 256>>>(bufC, meanc, rstdc, gc, bec, Wc2, bc2, out_ls);
}

// round 7
// speedup vs baseline: 1.2609x; 1.0198x over previous
#include <cuda_runtime.h>
#include <cuda_bf16.h>
#include <math.h>

#define NN 50000
#define EE 800000
#define OUTC 40
#define NTILE 196            // ceil(50000/256)

__device__ __align__(128) float g_scratch[29000000];

#define PACK2(dst, lo, hi) asm("mov.b64 %0, {%1, %2};" : "=l"(dst) : "f"(lo), "f"(hi))
#define UNPK2(lo, hi, v)   asm("mov.b64 {%0, %1}, %2;" : "=f"(lo), "=f"(hi) : "l"(v))
#define FMA2(acc, a, b)    asm("fma.rn.f32x2 %0, %1, %2, %0;" : "+l"(acc) : "l"(a), "l"(b))

// ======================= init: counts, flag, float stat accumulators =======
__global__ void init_kernel(int* c1, int* c2, int* flag64, float* statz) {
    int i = blockIdx.x * blockDim.x + threadIdx.x;
    if (i < NN) { c1[i] = 1; c2[i] = 0; }     // c1 starts at 1 (self-loop)
    if (i == 0) *flag64 = 1;
    if (i < 640) statz[i] = 0.f;
}

__global__ void detect_kernel(const int* __restrict__ w, int* flag64) {
    int any = 0;
    for (int i = blockIdx.x * blockDim.x + threadIdx.x; i < EE; i += gridDim.x * blockDim.x)
        any |= w[2 * i + 1];
    if (any) atomicAnd(flag64, 0);
}

// convert edge_index to int32 row/col AND histogram in one pass
__global__ void convert_hist_kernel(const int* __restrict__ w, const int* __restrict__ flag64,
                                    int* __restrict__ rowA, int* __restrict__ colA,
                                    int* c1, int* c2) {
    int e = blockIdx.x * blockDim.x + threadIdx.x;
    if (e >= EE) return;
    int r, c;
    if (*flag64) { r = w[2 * e]; c = w[2 * (EE + e)]; }
    else         { r = w[e];     c = w[EE + e]; }
    rowA[e] = r; colA[e] = c;
    atomicAdd(&c1[c], 1);
    atomicAdd(&c2[r], 1);
}

// ---- parallel 3-phase exclusive scan over two arrays (gridDim.y selects) ----
__global__ void scan_p1(const int* __restrict__ cnt1, const int* __restrict__ cnt2,
                        int* __restrict__ btot) {
    const int* cnt = blockIdx.y ? cnt2 : cnt1;
    __shared__ int sw[8];
    int idx = blockIdx.x * 256 + threadIdx.x;
    int v = (idx < NN) ? cnt[idx] : 0;
#pragma unroll
    for (int d = 16; d; d >>= 1) v += __shfl_xor_sync(0xffffffffu, v, d);
    if ((threadIdx.x & 31) == 0) sw[threadIdx.x >> 5] = v;
    __syncthreads();
    if (threadIdx.x == 0) {
        int s = 0;
#pragma unroll
        for (int i = 0; i < 8; i++) s += sw[i];
        btot[blockIdx.y * (NTILE + 1) + blockIdx.x] = s;
    }
}

__global__ void scan_p2(int* __restrict__ btot) {
    int* b = btot + blockIdx.y * (NTILE + 1);
    __shared__ int sw[8], sw2[9];
    int t = threadIdx.x, lane = t & 31, wid = t >> 5;
    int v = (t < NTILE) ? b[t] : 0;
    int inc = v;
#pragma unroll
    for (int d = 1; d < 32; d <<= 1) { int y = __shfl_up_sync(0xffffffffu, inc, d); if (lane >= d) inc += y; }
    if (lane == 31) sw[wid] = inc;
    __syncthreads();
    if (t == 0) { sw2[0] = 0; for (int i = 0; i < 8; i++) sw2[i + 1] = sw2[i] + sw[i]; }
    __syncthreads();
    int excl = sw2[wid] + inc - v;
    if (t < NTILE) b[t] = excl;
    if (t == 0) b[NTILE] = sw2[8];
}

// scan phase 3 + cursor init + self-loop placement
__global__ void scan_p3(const int* __restrict__ cnt1, const int* __restrict__ cnt2,
                        const int* __restrict__ btot,
                        int* __restrict__ off1, int* __restrict__ off2,
                        int* __restrict__ cur1, int* __restrict__ cur2, int* __restrict__ csr1) {
    const int* cnt = blockIdx.y ? cnt2 : cnt1;
    int* off = blockIdx.y ? off2 : off1;
    const int* b = btot + blockIdx.y * (NTILE + 1);
    __shared__ int sw[8], sw2[9];
    int t = threadIdx.x, lane = t & 31, wid = t >> 5;
    int idx = blockIdx.x * 256 + t;
    int v = (idx < NN) ? cnt[idx] : 0;
    int inc = v;
#pragma unroll
    for (int d = 1; d < 32; d <<= 1) { int y = __shfl_up_sync(0xffffffffu, inc, d); if (lane >= d) inc += y; }
    if (lane == 31) sw[wid] = inc;
    __syncthreads();
    if (t == 0) { sw2[0] = 0; for (int i = 0; i < 8; i++) sw2[i + 1] = sw2[i] + sw[i]; }
    __syncthreads();
    int excl = b[blockIdx.x] + sw2[wid] + inc - v;
    if (idx < NN) {
        off[idx] = excl;
        if (blockIdx.y == 0) { cur1[idx] = excl + 1; csr1[excl] = idx; }
        else                 cur2[idx] = excl;
    }
    if (blockIdx.x == 0 && t == 0) off[NN] = b[NTILE];
}

__global__ void fill_kernel(const int* __restrict__ rowA, const int* __restrict__ colA,
                            int* cur1, int* csr1,
                            int* cur2, int* csr2c, int* csr2e) {
    int e = blockIdx.x * blockDim.x + threadIdx.x;
    if (e >= EE) return;
    int r = rowA[e];
    int c = colA[e];
    int p = atomicAdd(&cur1[c], 1);
    csr1[p] = r;
    int q = atomicAdd(&cur2[r], 1);
    csr2c[q] = c;
    csr2e[q] = e;
}

// ======================= GEMM (K = 128 fixed, f32x2 FMA) ====================
// out[n][ocol+col] = sum_k A'[n][k] * W[wrow(col)*ldw + woff + wko(col) + k] + bias
// SPLITW: cols 0..63 -> Ws1 rows 0..63 k in [0,128); cols 64..127 -> same rows,
// k in [128,256) (merges the two edge-scorer GEMMs).

template <int TC, bool BNIN, bool ATTN, bool STATS, bool SPLITW>
__global__ void __launch_bounds__(128)
gemm_k128(const float* __restrict__ A, const float* __restrict__ W,
          int ldw, int woff, const float* __restrict__ bias,
          float* __restrict__ out, int opitch, int ocol, int nrows,
          const float* __restrict__ bnm, const float* __restrict__ bnr,
          const float* __restrict__ bng, const float* __restrict__ bnb,
          const float* __restrict__ as, const float* __restrict__ ad,
          float* __restrict__ asrc, float* __restrict__ adst,
          float* gsum, float* gsq) {
    constexpr int CT = TC / 16;
    constexpr int PA = 68;
    constexpr int PW = TC + 4;
    __shared__ float sA[32 * PA];
    __shared__ float sW[32 * PW];
    const int tid = threadIdx.x;
    const int trow = tid >> 4;     // 0..7
    const int tcol = tid & 15;     // 0..15
    const int r0 = blockIdx.x * 64;

    unsigned long long acc2[4][CT];   // row-pairs x cols
#pragma unroll
    for (int p = 0; p < 4; p++)
#pragma unroll
        for (int j = 0; j < CT; j++) acc2[p][j] = 0ull;

    for (int kb = 0; kb < 128; kb += 32) {
        float bm = 0.f, br = 0.f, bgm = 0.f, bbt = 0.f;
        if (BNIN) {
            int kf = kb + (tid & 31);
            bm = bnm[kf]; br = bnr[kf]; bgm = bng[kf]; bbt = bnb[kf];
        }
        __syncthreads();
#pragma unroll
        for (int i = 0; i < 16; i++) {
            int idx = tid + i * 128;
            int row = idx >> 5, kk = idx & 31;
            int gr = r0 + row;
            float v = (gr < nrows) ? A[(size_t)gr * 128 + kb + kk] : 0.f;
            if (BNIN && gr < nrows) {
                float t = (v - bm) * br * bgm + bbt;
                v = (t > 0.f) ? t : expm1f(t);
            }
            sA[kk * PA + row] = v;
        }
#pragma unroll
        for (int i = 0; i < (TC * 32) / 128; i++) {
            int idx = tid + i * 128;
            int col = idx >> 5, kk = idx & 31;
            int wrow = SPLITW ? (col & 63) : col;
            int wko  = SPLITW ? ((col >> 6) * 128) : 0;
            sW[kk * PW + col] = W[(size_t)wrow * ldw + woff + wko + kb + kk];
        }
        __syncthreads();
#pragma unroll
        for (int kk = 0; kk < 32; kk++) {
            float4 a0 = *(const float4*)&sA[kk * PA + trow * 8];
            float4 a1 = *(const float4*)&sA[kk * PA + trow * 8 + 4];
            unsigned long long ap[4];
            PACK2(ap[0], a0.x, a0.y);
            PACK2(ap[1], a0.z, a0.w);
            PACK2(ap[2], a1.x, a1.y);
            PACK2(ap[3], a1.z, a1.w);
            float w[CT];
#pragma unroll
            for (int j = 0; j < CT; j += 4) {
                float4 wv = *(const float4*)&sW[kk * PW + tcol * CT + j];
                w[j] = wv.x; w[j + 1] = wv.y; w[j + 2] = wv.z; w[j + 3] = wv.w;
            }
            unsigned long long wd[CT];
#pragma unroll
            for (int j = 0; j < CT; j++) PACK2(wd[j], w[j], w[j]);
#pragma unroll
            for (int p = 0; p < 4; p++)
#pragma unroll
                for (int j = 0; j < CT; j++) FMA2(acc2[p][j], ap[p], wd[j]);
        }
    }
    // ---- store ----
#pragma unroll
    for (int p = 0; p < 4; p++) {
        int gr0 = r0 + trow * 8 + 2 * p;
#pragma unroll
        for (int j = 0; j < CT; j++) {
            int col = tcol * CT + j;
            float b = bias ? bias[col] : 0.f;
            float lo, hi;
            UNPK2(lo, hi, acc2[p][j]);
            if (gr0 < nrows)     out[(size_t)gr0 * opitch + ocol + col]       = lo + b;
            if (gr0 + 1 < nrows) out[(size_t)(gr0 + 1) * opitch + ocol + col] = hi + b;
        }
    }
    // ---- fused attention dots (TC=128 only) ----
    if (ATTN) {
#pragma unroll
        for (int p = 0; p < 4; p++) {
            float s1lo = 0.f, s2lo = 0.f, s1hi = 0.f, s2hi = 0.f;
#pragma unroll
            for (int j = 0; j < CT; j++) {
                int col = tcol * CT + j;
                float aS = __ldg(&as[col]), aD = __ldg(&ad[col]);
                float lo, hi;
                UNPK2(lo, hi, acc2[p][j]);
                s1lo = fmaf(lo, aS, s1lo); s2lo = fmaf(lo, aD, s2lo);
                s1hi = fmaf(hi, aS, s1hi); s2hi = fmaf(hi, aD, s2hi);
            }
            s1lo += __shfl_xor_sync(0xffffffffu, s1lo, 1);
            s2lo += __shfl_xor_sync(0xffffffffu, s2lo, 1);
            s1hi += __shfl_xor_sync(0xffffffffu, s1hi, 1);
            s2hi += __shfl_xor_sync(0xffffffffu, s2hi, 1);
            if (!(tcol & 1)) {
                int h = tcol >> 1;
                int rlo = r0 + trow * 8 + 2 * p;
                if (rlo < nrows)     { asrc[rlo * 8 + h] = s1lo;       adst[rlo * 8 + h] = s2lo; }
                if (rlo + 1 < nrows) { asrc[(rlo + 1) * 8 + h] = s1hi; adst[(rlo + 1) * 8 + h] = s2hi; }
            }
        }
    }
    // ---- fused per-feature BN statistics ----
    if (STATS) {
        __shared__ float s_s[8][TC], s_q[8][TC];
#pragma unroll
        for (int j = 0; j < CT; j++) {
            int col = tcol * CT + j;
            float b = bias ? bias[col] : 0.f;
            float ps = 0.f, pq = 0.f;
#pragma unroll
            for (int p = 0; p < 4; p++) {
                int gr0 = r0 + trow * 8 + 2 * p;
                float lo, hi;
                UNPK2(lo, hi, acc2[p][j]);
                if (gr0 < nrows)     { float v = lo + b; ps += v; pq = fmaf(v, v, pq); }
                if (gr0 + 1 < nrows) { float v = hi + b; ps += v; pq = fmaf(v, v, pq); }
            }
            s_s[trow][col] = ps;
            s_q[trow][col] = pq;
        }
        __syncthreads();
        if (tid < TC) {
            float S = 0.f, Q = 0.f;
#pragma unroll
            for (int w = 0; w < 8; w++) { S += s_s[w][tid]; Q += s_q[w][tid]; }
            atomicAdd(&gsum[tid], S);
            atomicAdd(&gsq[tid],  Q);
        }
    }
}

// ======================= GAT aggregation (online softmax + BN stats) =======

__global__ void __launch_bounds__(256)
gat_aggregate(const float* __restrict__ hfeat,
              const float* __restrict__ asrc, const float* __restrict__ adst,
              const int* __restrict__ off, const int* __restrict__ csr,
              const float* __restrict__ bg, float* __restrict__ outp,
              float* gsum, float* gsq) {
    __shared__ float s_v[8][128];
    int gw = (blockIdx.x * blockDim.x + threadIdx.x) >> 5;
    int lane = threadIdx.x & 31;
    int wib = threadIdx.x >> 5;
    int head = lane >> 2;
    float ad = adst[gw * 8 + head];
    float mm = -INFINITY, den = 0.f;
    float4 acc = make_float4(0.f, 0.f, 0.f, 0.f);
    int s0 = off[gw], s1 = off[gw + 1];
    for (int i = s0; i < s1; i++) {
        int s = csr[i];
        float e = asrc[s * 8 + head] + ad;
        e = (e >= 0.f) ? e : 0.2f * e;
        if (e > mm) {
            float sc = __expf(mm - e);
            den *= sc;
            acc.x *= sc; acc.y *= sc; acc.z *= sc; acc.w *= sc;
            mm = e;
        }
        float p = __expf(e - mm);
        den += p;
        float4 hv = *(const float4*)&hfeat[(size_t)s * 128 + lane * 4];
        acc.x = fmaf(hv.x, p, acc.x);
        acc.y = fmaf(hv.y, p, acc.y);
        acc.z = fmaf(hv.z, p, acc.z);
        acc.w = fmaf(hv.w, p, acc.w);
    }
    float inv = 1.f / (den + 1e-16f);
    float4 bgv = *(const float4*)&bg[lane * 4];
    acc.x = fmaf(acc.x, inv, bgv.x);
    acc.y = fmaf(acc.y, inv, bgv.y);
    acc.z = fmaf(acc.z, inv, bgv.z);
    acc.w = fmaf(acc.w, inv, bgv.w);
    *(float4*)&outp[(size_t)gw * 128 + lane * 4] = acc;
    *(float4*)&s_v[wib][lane * 4] = acc;
    __syncthreads();
    int t = threadIdx.x;
    if (t < 128) {
        float S = 0.f, Q = 0.f;
#pragma unroll
        for (int w = 0; w < 8; w++) { float v = s_v[w][t]; S += v; Q = fmaf(v, v, Q); }
        atomicAdd(&gsum[t], S);
        atomicAdd(&gsq[t],  Q);
    }
}

// ======================= BN finalize + BN-ELU ==============================

__global__ void bn_finalize(const float* __restrict__ gs, const float* __restrict__ gq,
                            float* mean, float* rstd, int F) {
    int f = threadIdx.x;
    if (f < F) {
        double invN = 1.0 / (double)NN;
        double mu = (double)gs[f] * invN;
        double var = (double)gq[f] * invN - mu * mu;
        if (var < 0.0) var = 0.0;
        mean[f] = (float)mu;
        rstd[f] = rsqrtf((float)var + 1e-5f);
    }
}

__global__ void bn_elu_kernel(const float* __restrict__ x, const float* __restrict__ mean,
                              const float* __restrict__ rstd, const float* __restrict__ gamma,
                              const float* __restrict__ beta, float* __restrict__ out, int total) {
    int i = (blockIdx.x * blockDim.x + threadIdx.x) * 4;
    if (i >= total) return;
    float4 v = *(const float4*)&x[i];
    int f = i & 127;
    float r[4] = {v.x, v.y, v.z, v.w};
#pragma unroll
    for (int k = 0; k < 4; k++) {
        int ff = f + k;
        float t = (r[k] - mean[ff]) * rstd[ff] * gamma[ff] + beta[ff];
        r[k] = (t > 0.f) ? t : expm1f(t);
    }
    *(float4*)&out[i] = make_float4(r[0], r[1], r[2], r[3]);
}

// ======================= Edge scorer + gumbel gate =========================

__global__ void edge_logits_kernel(const float* __restrict__ prpc,
                                   const int* __restrict__ rowA, const int* __restrict__ colA,
                                   const float* __restrict__ gumbel,
                                   const float* __restrict__ bs1,
                                   const float* __restrict__ ws2,
                                   const float* __restrict__ bs2,
                                   float* __restrict__ wout, float* __restrict__ lrout) {
    __shared__ float sw2[64];
    __shared__ float sb1[64];
    if (threadIdx.x < 64) { sw2[threadIdx.x] = ws2[threadIdx.x]; sb1[threadIdx.x] = bs1[threadIdx.x]; }
    __syncthreads();
    int ge = (blockIdx.x * blockDim.x + threadIdx.x) >> 5;
    if (ge >= EE) return;
    int lane = threadIdx.x & 31;
    int r = rowA[ge];
    int c = colA[ge];
    float p0 = prpc[(size_t)r * 128 + lane]      + prpc[(size_t)c * 128 + 64 + lane] + sb1[lane];
    float p1 = prpc[(size_t)r * 128 + 32 + lane] + prpc[(size_t)c * 128 + 96 + lane] + sb1[32 + lane];
    p0 = fmaxf(p0, 0.f);
    p1 = fmaxf(p1, 0.f);
    float part = p0 * sw2[lane] + p1 * sw2[32 + lane];
#pragma unroll
    for (int d = 16; d; d >>= 1) part += __shfl_xor_sync(0xffffffffu, part, d);
    if (lane == 0) {
        float lr = part + bs2[0];
        lrout[ge] = lr;
        float g0 = gumbel[2 * (size_t)ge];
        float g1 = gumbel[2 * (size_t)ge + 1];
        wout[ge] = (lr + g1 > g0) ? 1.f : 0.f;
    }
}

// h_sparse = h_base + segment_sum(weights * h_base[col], row)
__global__ void sparse_agg_kernel(const float* __restrict__ hbase,
                                  const int* __restrict__ off2,
                                  const int* __restrict__ col, const int* __restrict__ eid,
                                  const float* __restrict__ w, float* __restrict__ outp) {
    int gw = (blockIdx.x * blockDim.x + threadIdx.x) >> 5;
    if (gw >= NN) return;
    int lane = threadIdx.x & 31;
    float4 acc = *(const float4*)&hbase[(size_t)gw * 128 + lane * 4];
    int s0 = off2[gw], s1 = off2[gw + 1];
    for (int i = s0; i < s1; i++) {
        int e = eid[i];
        if (w[e] != 0.f) {
            int c = col[i];
            float4 hv = *(const float4*)&hbase[(size_t)c * 128 + lane * 4];
            acc.x += hv.x; acc.y += hv.y; acc.z += hv.z; acc.w += hv.w;
        }
    }
    *(float4*)&outp[(size_t)gw * 128 + lane * 4] = acc;
}

// ======================= Classifier head ===================================

__global__ void __launch_bounds__(256)
classifier_kernel(const float* __restrict__ cpre, const float* __restrict__ mean,
                  const float* __restrict__ rstd, const float* __restrict__ gc,
                  const float* __restrict__ bec, const float* __restrict__ Wc2,
                  const float* __restrict__ bc2, float* __restrict__ outls) {
    __shared__ float sW[64 * 64];
    __shared__ float sb[40];
    __shared__ float sc[8][64];
    for (int idx = threadIdx.x; idx < 64 * 64; idx += blockDim.x) {
        int f = idx >> 6, j = idx & 63;
        sW[idx] = (j < 40) ? Wc2[j * 64 + f] : 0.f;
    }
    if (threadIdx.x < 40) sb[threadIdx.x] = bc2[threadIdx.x];
    __syncthreads();
    int gw = (blockIdx.x * blockDim.x + threadIdx.x) >> 5;
    int lane = threadIdx.x & 31;
    int wib = threadIdx.x >> 5;
    if (gw >= NN) return;
    float v0 = cpre[(size_t)gw * 64 + lane];
    float v1 = cpre[(size_t)gw * 64 + 32 + lane];
    int f0 = lane, f1 = lane + 32;
    sc[wib][lane]      = fmaxf((v0 - mean[f0]) * rstd[f0] * gc[f0] + bec[f0], 0.f);
    sc[wib][lane + 32] = fmaxf((v1 - mean[f1]) * rstd[f1] * gc[f1] + bec[f1], 0.f);
    __syncwarp();
    float l0 = sb[lane];
    float l1 = (lane < 8) ? sb[lane + 32] : 0.f;
#pragma unroll
    for (int f = 0; f < 64; f++) {
        float cv = sc[wib][f];
        l0 = fmaf(cv, sW[f * 64 + lane], l0);
        l1 = fmaf(cv, sW[f * 64 + lane + 32], l1);
    }
    float mx = fmaxf(l0, (lane < 8) ? l1 : -INFINITY);
#pragma unroll
    for (int d = 16; d; d >>= 1) mx = fmaxf(mx, __shfl_xor_sync(0xffffffffu, mx, d));
    float s = expf(l0 - mx) + ((lane < 8) ? expf(l1 - mx) : 0.f);
#pragma unroll
    for (int d = 16; d; d >>= 1) s += __shfl_xor_sync(0xffffffffu, s, d);
    float lse = mx + logf(s);
    outls[(size_t)gw * 40 + lane] = l0 - lse;
    if (lane < 8) outls[(size_t)gw * 40 + 32 + lane] = l1 - lse;
}

// ======================= Host orchestration ================================

extern "C" void kernel_launch(void* const* d_in, const int* in_sizes, int n_in,
                              void* d_out, int out_size) {
    (void)in_sizes; (void)n_in; (void)out_size;

    float* S = nullptr;
    cudaGetSymbolAddress((void**)&S, g_scratch);

    float* bufA = S;                       // N*128
    float* bufH = S + 6400000;             // N*128
    float* bufG = S + 12800000;            // N*128
    float* bufC = S + 19200000;            // N*64
    float* asrc = S + 22400000;            // N*8
    float* adst = S + 22800000;
    float* fpar = S + 23200000;
    float* mean1 = fpar,       * rstd1 = fpar + 128;
    float* mean2 = fpar + 256, * rstd2 = fpar + 384;
    float* meanc = fpar + 512, * rstdc = fpar + 640;
    float* stat  = S + 23201024;
    float* s1s = stat,       * s1q = stat + 128;
    float* s2s = stat + 256, * s2q = stat + 384;
    float* scs = stat + 512, * scq = stat + 576;
    int* ip    = (int*)(S + 24000000);
    int* rowA  = ip;
    int* colA  = rowA + EE;
    int* off1  = colA + EE;
    int* off2  = off1 + (NN + 1);
    int* cur1  = off2 + (NN + 1);
    int* cur2  = cur1 + NN;
    int* cnt1  = cur2 + NN;
    int* cnt2  = cnt1 + NN;
    int* csr1  = cnt2 + NN;
    int* csr2c = csr1 + (EE + NN);
    int* csr2e = csr2c + EE;
    int* flag64 = csr2e + EE;
    int* btot   = flag64 + 1;

    const float* x      = (const float*)d_in[0];
    const int*   eiw    = (const int*)d_in[1];
    const float* gumbel = (const float*)d_in[2];
    const float* W_res  = (const float*)d_in[3];
    const float* b_res  = (const float*)d_in[4];
    const float* Wg1    = (const float*)d_in[5];
    const float* as1    = (const float*)d_in[6];
    const float* ad1    = (const float*)d_in[7];
    const float* bg1    = (const float*)d_in[8];
    const float* g1     = (const float*)d_in[9];
    const float* be1    = (const float*)d_in[10];
    const float* Wg2    = (const float*)d_in[11];
    const float* as2    = (const float*)d_in[12];
    const float* ad2    = (const float*)d_in[13];
    const float* bg2    = (const float*)d_in[14];
    const float* g2     = (const float*)d_in[15];
    const float* be2    = (const float*)d_in[16];
    const float* Ws1    = (const float*)d_in[17];
    const float* bs1    = (const float*)d_in[18];
    const float* Ws2    = (const float*)d_in[19];
    const float* bs2    = (const float*)d_in[20];
    const float* Wc1    = (const float*)d_in[21];
    const float* bc1    = (const float*)d_in[22];
    const float* gc     = (const float*)d_in[23];
    const float* bec    = (const float*)d_in[24];
    const float* Wc2    = (const float*)d_in[25];
    const float* bc2    = (const float*)d_in[26];

    float* out_ls = (float*)d_out;
    float* out_w  = out_ls + (size_t)NN * OUTC;
    float* out_lr = out_w + EE;

    const int NB   = (NN + 255) / 256;
    const int EB   = (EE + 255) / 256;
    const int WRPN = (NN * 32) / 256;
    const int WRPE = (EE * 32) / 256;
    const int GEMG = (NN + 63) / 64;

    // ---- fork: CSR build on side stream, GEMMs on main stream ----
    cudaStream_t s1str;
    cudaEvent_t evFork, evJoin;
    cudaStreamCreateWithFlags(&s1str, cudaStreamNonBlocking);
    cudaEventCreateWithFlags(&evFork, cudaEventDisableTiming);
    cudaEventCreateWithFlags(&evJoin, cudaEventDisableTiming);

    cudaEventRecord(evFork, 0);
    cudaStreamWaitEvent(s1str, evFork, 0);

    // side stream: CSR build chain
    init_kernel<<<NB, 256, 0, s1str>>>(cnt1, cnt2, flag64, stat);
    detect_kernel<<<256, 256, 0, s1str>>>(eiw, flag64);
    convert_hist_kernel<<<EB, 256, 0, s1str>>>(eiw, flag64, rowA, colA, cnt1, cnt2);
    scan_p1<<<dim3(NTILE, 2), 256, 0, s1str>>>(cnt1, cnt2, btot);
    scan_p2<<<dim3(1, 2), 256, 0, s1str>>>(btot);
    scan_p3<<<dim3(NTILE, 2), 256, 0, s1str>>>(cnt1, cnt2, btot, off1, off2, cur1, cur2, csr1);
    fill_kernel<<<EB, 256, 0, s1str>>>(rowA, colA, cur1, csr1, cur2, csr2c, csr2e);
    cudaEventRecord(evJoin, s1str);

    // main stream: x_proj, Wg1-GEMM (+fused attention dots)
    gemm_k128<128, false, false, false, false><<<GEMG, 128>>>(
        x, W_res, 128, 0, b_res, bufA, 128, 0, NN,
        nullptr, nullptr, nullptr, nullptr, nullptr, nullptr, nullptr, nullptr, nullptr, nullptr);
    gemm_k128<128, false, true, false, false><<<GEMG, 128>>>(
        bufA, Wg1, 128, 0, nullptr, bufH, 128, 0, NN,
        nullptr, nullptr, nullptr, nullptr, as1, ad1, asrc, adst, nullptr, nullptr);

    // join: aggregation needs CSR + stats-zeroing from side stream
    cudaStreamWaitEvent(0, evJoin, 0);

    gat_aggregate<<<WRPN, 256>>>(bufH, asrc, adst, off1, csr1, bg1, bufG, s1s, s1q);
    bn_finalize<<<1, 128>>>(s1s, s1q, mean1, rstd1, 128);

    // GAT layer 2 (BN+ELU of layer1 fused into A-load)
    gemm_k128<128, true, true, false, false><<<GEMG, 128>>>(
        bufG, Wg2, 128, 0, nullptr, bufH, 128, 0, NN,
        mean1, rstd1, g1, be1, as2, ad2, asrc, adst, nullptr, nullptr);
    gat_aggregate<<<WRPN, 256>>>(bufH, asrc, adst, off1, csr1, bg2, bufG, s2s, s2q);
    bn_finalize<<<1, 128>>>(s2s, s2q, mean2, rstd2, 128);
    bn_elu_kernel<<<(NN * 32 + 255) / 256, 256>>>(bufG, mean2, rstd2, g2, be2, bufA, NN * 128);
    // bufA = h_base

    // edge scorer: single merged SPLITW GEMM (pr | pc)
    gemm_k128<128, false, false, false, true><<<GEMG, 128>>>(
        bufA, Ws1, 256, 0, nullptr, bufH, 128, 0, NN,
        nullptr, nullptr, nullptr, nullptr, nullptr, nullptr, nullptr, nullptr, nullptr, nullptr);
    edge_logits_kernel<<<WRPE, 256>>>(bufH, rowA, colA, gumbel, bs1, Ws2, bs2, out_w, out_lr);

    // sparse aggregation
    sparse_agg_kernel<<<WRPN, 256>>>(bufA, off2, csr2c, csr2e, out_w, bufG);

    // classifier (BN stats fused into GEMM)
    gemm_k128<64, false, false, true, false><<<GEMG, 128>>>(
        bufG, Wc1, 128, 0, bc1, bufC, 64, 0, NN,
        nullptr, nullptr, nullptr, nullptr, nullptr, nullptr, nullptr, nullptr, scs, scq);
    bn_finalize<<<1, 64>>>(scs, scq, meanc, rstdc, 64);
    classifier_kernel<<<WRPN, 256>>>(bufC, meanc, rstdc, gc, bec, Wc2, bc2, out_ls);
}

// round 8
// speedup vs baseline: 1.3534x; 1.0734x over previous
#include <cuda_runtime.h>
#include <cuda_bf16.h>
#include <math.h>

#define NN 50000
#define EE 800000
#define OUTC 40
#define NTILE 196            // ceil(50000/256)

__device__ __align__(128) float g_scratch[29000000];

#define PACK2(dst, lo, hi) asm("mov.b64 %0, {%1, %2};" : "=l"(dst) : "f"(lo), "f"(hi))
#define UNPK2(lo, hi, v)   asm("mov.b64 {%0, %1}, %2;" : "=f"(lo), "=f"(hi) : "l"(v))
#define FMA2(acc, a, b)    asm("fma.rn.f32x2 %0, %1, %2, %0;" : "+l"(acc) : "l"(a), "l"(b))

// ======================= init: counts, flag, float stat accumulators =======
__global__ void init_kernel(int* c1, int* c2, int* flag64, float* statz) {
    int i = blockIdx.x * blockDim.x + threadIdx.x;
    if (i < NN) { c1[i] = 1; c2[i] = 0; }     // c1 starts at 1 (self-loop)
    if (i == 0) *flag64 = 1;
    if (i < 640) statz[i] = 0.f;
}

__global__ void detect_kernel(const int* __restrict__ w, int* flag64) {
    int any = 0;
    for (int i = blockIdx.x * blockDim.x + threadIdx.x; i < EE; i += gridDim.x * blockDim.x)
        any |= w[2 * i + 1];
    if (any) atomicAnd(flag64, 0);
}

// convert edge_index to int32 row/col AND histogram in one pass
__global__ void convert_hist_kernel(const int* __restrict__ w, const int* __restrict__ flag64,
                                    int* __restrict__ rowA, int* __restrict__ colA,
                                    int* c1, int* c2) {
    int e = blockIdx.x * blockDim.x + threadIdx.x;
    if (e >= EE) return;
    int r, c;
    if (*flag64) { r = w[2 * e]; c = w[2 * (EE + e)]; }
    else         { r = w[e];     c = w[EE + e]; }
    rowA[e] = r; colA[e] = c;
    atomicAdd(&c1[c], 1);
    atomicAdd(&c2[r], 1);
}

// ---- parallel 3-phase exclusive scan over two arrays (gridDim.y selects) ----
__global__ void scan_p1(const int* __restrict__ cnt1, const int* __restrict__ cnt2,
                        int* __restrict__ btot) {
    const int* cnt = blockIdx.y ? cnt2 : cnt1;
    __shared__ int sw[8];
    int idx = blockIdx.x * 256 + threadIdx.x;
    int v = (idx < NN) ? cnt[idx] : 0;
#pragma unroll
    for (int d = 16; d; d >>= 1) v += __shfl_xor_sync(0xffffffffu, v, d);
    if ((threadIdx.x & 31) == 0) sw[threadIdx.x >> 5] = v;
    __syncthreads();
    if (threadIdx.x == 0) {
        int s = 0;
#pragma unroll
        for (int i = 0; i < 8; i++) s += sw[i];
        btot[blockIdx.y * (NTILE + 1) + blockIdx.x] = s;
    }
}

__global__ void scan_p2(int* __restrict__ btot) {
    int* b = btot + blockIdx.y * (NTILE + 1);
    __shared__ int sw[8], sw2[9];
    int t = threadIdx.x, lane = t & 31, wid = t >> 5;
    int v = (t < NTILE) ? b[t] : 0;
    int inc = v;
#pragma unroll
    for (int d = 1; d < 32; d <<= 1) { int y = __shfl_up_sync(0xffffffffu, inc, d); if (lane >= d) inc += y; }
    if (lane == 31) sw[wid] = inc;
    __syncthreads();
    if (t == 0) { sw2[0] = 0; for (int i = 0; i < 8; i++) sw2[i + 1] = sw2[i] + sw[i]; }
    __syncthreads();
    int excl = sw2[wid] + inc - v;
    if (t < NTILE) b[t] = excl;
    if (t == 0) b[NTILE] = sw2[8];
}

// scan phase 3 + cursor init + self-loop placement
__global__ void scan_p3(const int* __restrict__ cnt1, const int* __restrict__ cnt2,
                        const int* __restrict__ btot,
                        int* __restrict__ off1, int* __restrict__ off2,
                        int* __restrict__ cur1, int* __restrict__ cur2, int* __restrict__ csr1) {
    const int* cnt = blockIdx.y ? cnt2 : cnt1;
    int* off = blockIdx.y ? off2 : off1;
    const int* b = btot + blockIdx.y * (NTILE + 1);
    __shared__ int sw[8], sw2[9];
    int t = threadIdx.x, lane = t & 31, wid = t >> 5;
    int idx = blockIdx.x * 256 + t;
    int v = (idx < NN) ? cnt[idx] : 0;
    int inc = v;
#pragma unroll
    for (int d = 1; d < 32; d <<= 1) { int y = __shfl_up_sync(0xffffffffu, inc, d); if (lane >= d) inc += y; }
    if (lane == 31) sw[wid] = inc;
    __syncthreads();
    if (t == 0) { sw2[0] = 0; for (int i = 0; i < 8; i++) sw2[i + 1] = sw2[i] + sw[i]; }
    __syncthreads();
    int excl = b[blockIdx.x] + sw2[wid] + inc - v;
    if (idx < NN) {
        off[idx] = excl;
        if (blockIdx.y == 0) { cur1[idx] = excl + 1; csr1[excl] = idx; }
        else                 cur2[idx] = excl;
    }
    if (blockIdx.x == 0 && t == 0) off[NN] = b[NTILE];
}

__global__ void fill_kernel(const int* __restrict__ rowA, const int* __restrict__ colA,
                            int* cur1, int* csr1,
                            int* cur2, int* csr2c, int* csr2e) {
    int e = blockIdx.x * blockDim.x + threadIdx.x;
    if (e >= EE) return;
    int r = rowA[e];
    int c = colA[e];
    int p = atomicAdd(&cur1[c], 1);
    csr1[p] = r;
    int q = atomicAdd(&cur2[r], 1);
    csr2c[q] = c;
    csr2e[q] = e;
}

// ======================= weight fusion: Wf = Wg1 @ W_res, bf = Wg1 @ b_res ==
__global__ void wfuse_kernel(const float* __restrict__ Wg1, const float* __restrict__ W_res,
                             const float* __restrict__ b_res,
                             float* __restrict__ Wf, float* __restrict__ bf) {
    __shared__ float sWg[128];
    __shared__ float red[128];
    int d = blockIdx.x, k = threadIdx.x;
    sWg[k] = Wg1[d * 128 + k];
    __syncthreads();
    float s = 0.f;
#pragma unroll 8
    for (int j = 0; j < 128; j++) s = fmaf(sWg[j], W_res[j * 128 + k], s);
    Wf[d * 128 + k] = s;
    red[k] = sWg[k] * b_res[k];
    __syncthreads();
    for (int st = 64; st; st >>= 1) { if (k < st) red[k] += red[k + st]; __syncthreads(); }
    if (k == 0) bf[d] = red[0];
}

// ======================= GEMM (K = 128 fixed, f32x2 FMA) ====================
// out[n][ocol+col] = sum_k A'[n][k] * W[wrow(col)*ldw + woff + wko(col) + k] + bias
// SPLITW merges the two edge-scorer GEMMs into one TC=128 launch.

template <int TC, bool BNIN, bool ATTN, bool STATS, bool SPLITW>
__global__ void __launch_bounds__(128, 4)
gemm_k128(const float* __restrict__ A, const float* __restrict__ W,
          int ldw, int woff, const float* __restrict__ bias,
          float* __restrict__ out, int opitch, int ocol, int nrows,
          const float* __restrict__ bnm, const float* __restrict__ bnr,
          const float* __restrict__ bng, const float* __restrict__ bnb,
          const float* __restrict__ as, const float* __restrict__ ad,
          float* __restrict__ asrc, float* __restrict__ adst,
          float* gsum, float* gsq) {
    constexpr int CT = TC / 16;
    constexpr int PA = 68;
    constexpr int PW = TC + 4;
    __shared__ float sA[32 * PA];
    __shared__ float sW[32 * PW];
    const int tid = threadIdx.x;
    const int trow = tid >> 4;     // 0..7
    const int tcol = tid & 15;     // 0..15
    const int r0 = blockIdx.x * 64;

    unsigned long long acc2[4][CT];   // row-pairs x cols
#pragma unroll
    for (int p = 0; p < 4; p++)
#pragma unroll
        for (int j = 0; j < CT; j++) acc2[p][j] = 0ull;

    for (int kb = 0; kb < 128; kb += 32) {
        float bm = 0.f, br = 0.f, bgm = 0.f, bbt = 0.f;
        if (BNIN) {
            int kf = kb + (tid & 31);
            bm = bnm[kf]; br = bnr[kf]; bgm = bng[kf]; bbt = bnb[kf];
        }
        __syncthreads();
#pragma unroll
        for (int i = 0; i < 16; i++) {
            int idx = tid + i * 128;
            int row = idx >> 5, kk = idx & 31;
            int gr = r0 + row;
            float v = (gr < nrows) ? A[(size_t)gr * 128 + kb + kk] : 0.f;
            if (BNIN && gr < nrows) {
                float t = (v - bm) * br * bgm + bbt;
                v = (t > 0.f) ? t : expm1f(t);
            }
            sA[kk * PA + row] = v;
        }
#pragma unroll
        for (int i = 0; i < (TC * 32) / 128; i++) {
            int idx = tid + i * 128;
            int col = idx >> 5, kk = idx & 31;
            int wrow = SPLITW ? (col & 63) : col;
            int wko  = SPLITW ? ((col >> 6) * 128) : 0;
            sW[kk * PW + col] = W[(size_t)wrow * ldw + woff + wko + kb + kk];
        }
        __syncthreads();
#pragma unroll
        for (int kk = 0; kk < 32; kk++) {
            // row pairs are adjacent in sA -> direct 64-bit loads, no packing
            unsigned long long ap[4];
#pragma unroll
            for (int p = 0; p < 4; p++)
                ap[p] = *(const unsigned long long*)&sA[kk * PA + trow * 8 + 2 * p];
            float w[CT];
#pragma unroll
            for (int j = 0; j < CT; j += 4) {
                float4 wv = *(const float4*)&sW[kk * PW + tcol * CT + j];
                w[j] = wv.x; w[j + 1] = wv.y; w[j + 2] = wv.z; w[j + 3] = wv.w;
            }
            unsigned long long wd[CT];
#pragma unroll
            for (int j = 0; j < CT; j++) PACK2(wd[j], w[j], w[j]);
#pragma unroll
            for (int p = 0; p < 4; p++)
#pragma unroll
                for (int j = 0; j < CT; j++) FMA2(acc2[p][j], ap[p], wd[j]);
        }
    }
    // ---- store ----
#pragma unroll
    for (int p = 0; p < 4; p++) {
        int gr0 = r0 + trow * 8 + 2 * p;
#pragma unroll
        for (int j = 0; j < CT; j++) {
            int col = tcol * CT + j;
            float b = bias ? bias[col] : 0.f;
            float lo, hi;
            UNPK2(lo, hi, acc2[p][j]);
            if (gr0 < nrows)     out[(size_t)gr0 * opitch + ocol + col]       = lo + b;
            if (gr0 + 1 < nrows) out[(size_t)(gr0 + 1) * opitch + ocol + col] = hi + b;
        }
    }
    // ---- fused attention dots (TC=128 only) ----
    if (ATTN) {
#pragma unroll
        for (int p = 0; p < 4; p++) {
            float s1lo = 0.f, s2lo = 0.f, s1hi = 0.f, s2hi = 0.f;
#pragma unroll
            for (int j = 0; j < CT; j++) {
                int col = tcol * CT + j;
                float aS = __ldg(&as[col]), aD = __ldg(&ad[col]);
                float lo, hi;
                UNPK2(lo, hi, acc2[p][j]);
                s1lo = fmaf(lo, aS, s1lo); s2lo = fmaf(lo, aD, s2lo);
                s1hi = fmaf(hi, aS, s1hi); s2hi = fmaf(hi, aD, s2hi);
            }
            s1lo += __shfl_xor_sync(0xffffffffu, s1lo, 1);
            s2lo += __shfl_xor_sync(0xffffffffu, s2lo, 1);
            s1hi += __shfl_xor_sync(0xffffffffu, s1hi, 1);
            s2hi += __shfl_xor_sync(0xffffffffu, s2hi, 1);
            if (!(tcol & 1)) {
                int h = tcol >> 1;
                int rlo = r0 + trow * 8 + 2 * p;
                if (rlo < nrows)     { asrc[rlo * 8 + h] = s1lo;       adst[rlo * 8 + h] = s2lo; }
                if (rlo + 1 < nrows) { asrc[(rlo + 1) * 8 + h] = s1hi; adst[(rlo + 1) * 8 + h] = s2hi; }
            }
        }
    }
    // ---- fused per-feature BN statistics ----
    if (STATS) {
        __shared__ float s_s[8][TC], s_q[8][TC];
#pragma unroll
        for (int j = 0; j < CT; j++) {
            int col = tcol * CT + j;
            float b = bias ? bias[col] : 0.f;
            float ps = 0.f, pq = 0.f;
#pragma unroll
            for (int p = 0; p < 4; p++) {
                int gr0 = r0 + trow * 8 + 2 * p;
                float lo, hi;
                UNPK2(lo, hi, acc2[p][j]);
                if (gr0 < nrows)     { float v = lo + b; ps += v; pq = fmaf(v, v, pq); }
                if (gr0 + 1 < nrows) { float v = hi + b; ps += v; pq = fmaf(v, v, pq); }
            }
            s_s[trow][col] = ps;
            s_q[trow][col] = pq;
        }
        __syncthreads();
        if (tid < TC) {
            float S = 0.f, Q = 0.f;
#pragma unroll
            for (int w = 0; w < 8; w++) { S += s_s[w][tid]; Q += s_q[w][tid]; }
            atomicAdd(&gsum[tid], S);
            atomicAdd(&gsq[tid],  Q);
        }
    }
}

// ======================= GAT aggregation (online softmax + BN stats) =======

__global__ void __launch_bounds__(256)
gat_aggregate(const float* __restrict__ hfeat,
              const float* __restrict__ asrc, const float* __restrict__ adst,
              const int* __restrict__ off, const int* __restrict__ csr,
              const float* __restrict__ bg, float* __restrict__ outp,
              float* gsum, float* gsq) {
    __shared__ float s_v[8][128];
    int gw = (blockIdx.x * blockDim.x + threadIdx.x) >> 5;
    int lane = threadIdx.x & 31;
    int wib = threadIdx.x >> 5;
    int head = lane >> 2;
    float ad = adst[gw * 8 + head];
    float mm = -INFINITY, den = 0.f;
    float4 acc = make_float4(0.f, 0.f, 0.f, 0.f);
    int s0 = off[gw], s1 = off[gw + 1];
    for (int i = s0; i < s1; i++) {
        int s = csr[i];
        float e = asrc[s * 8 + head] + ad;
        e = (e >= 0.f) ? e : 0.2f * e;
        if (e > mm) {
            float sc = __expf(mm - e);
            den *= sc;
            acc.x *= sc; acc.y *= sc; acc.z *= sc; acc.w *= sc;
            mm = e;
        }
        float p = __expf(e - mm);
        den += p;
        float4 hv = *(const float4*)&hfeat[(size_t)s * 128 + lane * 4];
        acc.x = fmaf(hv.x, p, acc.x);
        acc.y = fmaf(hv.y, p, acc.y);
        acc.z = fmaf(hv.z, p, acc.z);
        acc.w = fmaf(hv.w, p, acc.w);
    }
    float inv = 1.f / (den + 1e-16f);
    float4 bgv = *(const float4*)&bg[lane * 4];
    acc.x = fmaf(acc.x, inv, bgv.x);
    acc.y = fmaf(acc.y, inv, bgv.y);
    acc.z = fmaf(acc.z, inv, bgv.z);
    acc.w = fmaf(acc.w, inv, bgv.w);
    *(float4*)&outp[(size_t)gw * 128 + lane * 4] = acc;
    *(float4*)&s_v[wib][lane * 4] = acc;
    __syncthreads();
    int t = threadIdx.x;
    if (t < 128) {
        float S = 0.f, Q = 0.f;
#pragma unroll
        for (int w = 0; w < 8; w++) { float v = s_v[w][t]; S += v; Q = fmaf(v, v, Q); }
        atomicAdd(&gsum[t], S);
        atomicAdd(&gsq[t],  Q);
    }
}

// ======================= BN finalize + BN-ELU ==============================

__global__ void bn_finalize(const float* __restrict__ gs, const float* __restrict__ gq,
                            float* mean, float* rstd, int F) {
    int f = threadIdx.x;
    if (f < F) {
        double invN = 1.0 / (double)NN;
        double mu = (double)gs[f] * invN;
        double var = (double)gq[f] * invN - mu * mu;
        if (var < 0.0) var = 0.0;
        mean[f] = (float)mu;
        rstd[f] = rsqrtf((float)var + 1e-5f);
    }
}

__global__ void bn_elu_kernel(const float* __restrict__ x, const float* __restrict__ mean,
                              const float* __restrict__ rstd, const float* __restrict__ gamma,
                              const float* __restrict__ beta, float* __restrict__ out, int total) {
    int i = (blockIdx.x * blockDim.x + threadIdx.x) * 4;
    if (i >= total) return;
    float4 v = *(const float4*)&x[i];
    int f = i & 127;
    float r[4] = {v.x, v.y, v.z, v.w};
#pragma unroll
    for (int k = 0; k < 4; k++) {
        int ff = f + k;
        float t = (r[k] - mean[ff]) * rstd[ff] * gamma[ff] + beta[ff];
        r[k] = (t > 0.f) ? t : expm1f(t);
    }
    *(float4*)&out[i] = make_float4(r[0], r[1], r[2], r[3]);
}

// ======================= Edge scorer + gumbel gate =========================

__global__ void edge_logits_kernel(const float* __restrict__ prpc,
                                   const int* __restrict__ rowA, const int* __restrict__ colA,
                                   const float* __restrict__ gumbel,
                                   const float* __restrict__ bs1,
                                   const float* __restrict__ ws2,
                                   const float* __restrict__ bs2,
                                   float* __restrict__ wout, float* __restrict__ lrout) {
    __shared__ float sw2[64];
    __shared__ float sb1[64];
    if (threadIdx.x < 64) { sw2[threadIdx.x] = ws2[threadIdx.x]; sb1[threadIdx.x] = bs1[threadIdx.x]; }
    __syncthreads();
    int ge = (blockIdx.x * blockDim.x + threadIdx.x) >> 5;
    if (ge >= EE) return;
    int lane = threadIdx.x & 31;
    int r = rowA[ge];
    int c = colA[ge];
    float p0 = prpc[(size_t)r * 128 + lane]      + prpc[(size_t)c * 128 + 64 + lane] + sb1[lane];
    float p1 = prpc[(size_t)r * 128 + 32 + lane] + prpc[(size_t)c * 128 + 96 + lane] + sb1[32 + lane];
    p0 = fmaxf(p0, 0.f);
    p1 = fmaxf(p1, 0.f);
    float part = p0 * sw2[lane] + p1 * sw2[32 + lane];
#pragma unroll
    for (int d = 16; d; d >>= 1) part += __shfl_xor_sync(0xffffffffu, part, d);
    if (lane == 0) {
        float lr = part + bs2[0];
        lrout[ge] = lr;
        float g0 = gumbel[2 * (size_t)ge];
        float g1 = gumbel[2 * (size_t)ge + 1];
        wout[ge] = (lr + g1 > g0) ? 1.f : 0.f;
    }
}

// h_sparse = h_base + segment_sum(weights * h_base[col], row)
__global__ void sparse_agg_kernel(const float* __restrict__ hbase,
                                  const int* __restrict__ off2,
                                  const int* __restrict__ col, const int* __restrict__ eid,
                                  const float* __restrict__ w, float* __restrict__ outp) {
    int gw = (blockIdx.x * blockDim.x + threadIdx.x) >> 5;
    if (gw >= NN) return;
    int lane = threadIdx.x & 31;
    float4 acc = *(const float4*)&hbase[(size_t)gw * 128 + lane * 4];
    int s0 = off2[gw], s1 = off2[gw + 1];
    for (int i = s0; i < s1; i++) {
        int e = eid[i];
        if (w[e] != 0.f) {
            int c = col[i];
            float4 hv = *(const float4*)&hbase[(size_t)c * 128 + lane * 4];
            acc.x += hv.x; acc.y += hv.y; acc.z += hv.z; acc.w += hv.w;
        }
    }
    *(float4*)&outp[(size_t)gw * 128 + lane * 4] = acc;
}

// ======================= Classifier head ===================================

__global__ void __launch_bounds__(256)
classifier_kernel(const float* __restrict__ cpre, const float* __restrict__ mean,
                  const float* __restrict__ rstd, const float* __restrict__ gc,
                  const float* __restrict__ bec, const float* __restrict__ Wc2,
                  const float* __restrict__ bc2, float* __restrict__ outls) {
    __shared__ float sW[64 * 64];
    __shared__ float sb[40];
    __shared__ float sc[8][64];
    for (int idx = threadIdx.x; idx < 64 * 64; idx += blockDim.x) {
        int f = idx >> 6, j = idx & 63;
        sW[idx] = (j < 40) ? Wc2[j * 64 + f] : 0.f;
    }
    if (threadIdx.x < 40) sb[threadIdx.x] = bc2[threadIdx.x];
    __syncthreads();
    int gw = (blockIdx.x * blockDim.x + threadIdx.x) >> 5;
    int lane = threadIdx.x & 31;
    int wib = threadIdx.x >> 5;
    if (gw >= NN) return;
    float v0 = cpre[(size_t)gw * 64 + lane];
    float v1 = cpre[(size_t)gw * 64 + 32 + lane];
    int f0 = lane, f1 = lane + 32;
    sc[wib][lane]      = fmaxf((v0 - mean[f0]) * rstd[f0] * gc[f0] + bec[f0], 0.f);
    sc[wib][lane + 32] = fmaxf((v1 - mean[f1]) * rstd[f1] * gc[f1] + bec[f1], 0.f);
    __syncwarp();
    float l0 = sb[lane];
    float l1 = (lane < 8) ? sb[lane + 32] : 0.f;
#pragma unroll
    for (int f = 0; f < 64; f++) {
        float cv = sc[wib][f];
        l0 = fmaf(cv, sW[f * 64 + lane], l0);
        l1 = fmaf(cv, sW[f * 64 + lane + 32], l1);
    }
    float mx = fmaxf(l0, (lane < 8) ? l1 : -INFINITY);
#pragma unroll
    for (int d = 16; d; d >>= 1) mx = fmaxf(mx, __shfl_xor_sync(0xffffffffu, mx, d));
    float s = expf(l0 - mx) + ((lane < 8) ? expf(l1 - mx) : 0.f);
#pragma unroll
    for (int d = 16; d; d >>= 1) s += __shfl_xor_sync(0xffffffffu, s, d);
    float lse = mx + logf(s);
    outls[(size_t)gw * 40 + lane] = l0 - lse;
    if (lane < 8) outls[(size_t)gw * 40 + 32 + lane] = l1 - lse;
}

// ======================= Host orchestration ================================

extern "C" void kernel_launch(void* const* d_in, const int* in_sizes, int n_in,
                              void* d_out, int out_size) {
    (void)in_sizes; (void)n_in; (void)out_size;

    float* S = nullptr;
    cudaGetSymbolAddress((void**)&S, g_scratch);

    float* bufA = S;                       // N*128
    float* bufH = S + 6400000;             // N*128
    float* bufG = S + 12800000;            // N*128
    float* bufC = S + 19200000;            // N*64
    float* asrc = S + 22400000;            // N*8
    float* adst = S + 22800000;
    float* fpar = S + 23200000;
    float* mean1 = fpar,       * rstd1 = fpar + 128;
    float* mean2 = fpar + 256, * rstd2 = fpar + 384;
    float* meanc = fpar + 512, * rstdc = fpar + 640;
    float* stat  = S + 23201024;
    float* s1s = stat,       * s1q = stat + 128;
    float* s2s = stat + 256, * s2q = stat + 384;
    float* scs = stat + 512, * scq = stat + 576;
    float* Wf   = S + 23300000;            // 128*128 fused weight
    float* bf   = Wf + 16384;              // 128 fused bias
    int* ip    = (int*)(S + 24000000);
    int* rowA  = ip;
    int* colA  = rowA + EE;
    int* off1  = colA + EE;
    int* off2  = off1 + (NN + 1);
    int* cur1  = off2 + (NN + 1);
    int* cur2  = cur1 + NN;
    int* cnt1  = cur2 + NN;
    int* cnt2  = cnt1 + NN;
    int* csr1  = cnt2 + NN;
    int* csr2c = csr1 + (EE + NN);
    int* csr2e = csr2c + EE;
    int* flag64 = csr2e + EE;
    int* btot   = flag64 + 1;

    const float* x      = (const float*)d_in[0];
    const int*   eiw    = (const int*)d_in[1];
    const float* gumbel = (const float*)d_in[2];
    const float* W_res  = (const float*)d_in[3];
    const float* b_res  = (const float*)d_in[4];
    const float* Wg1    = (const float*)d_in[5];
    const float* as1    = (const float*)d_in[6];
    const float* ad1    = (const float*)d_in[7];
    const float* bg1    = (const float*)d_in[8];
    const float* g1     = (const float*)d_in[9];
    const float* be1    = (const float*)d_in[10];
    const float* Wg2    = (const float*)d_in[11];
    const float* as2    = (const float*)d_in[12];
    const float* ad2    = (const float*)d_in[13];
    const float* bg2    = (const float*)d_in[14];
    const float* g2     = (const float*)d_in[15];
    const float* be2    = (const float*)d_in[16];
    const float* Ws1    = (const float*)d_in[17];
    const float* bs1    = (const float*)d_in[18];
    const float* Ws2    = (const float*)d_in[19];
    const float* bs2    = (const float*)d_in[20];
    const float* Wc1    = (const float*)d_in[21];
    const float* bc1    = (const float*)d_in[22];
    const float* gc     = (const float*)d_in[23];
    const float* bec    = (const float*)d_in[24];
    const float* Wc2    = (const float*)d_in[25];
    const float* bc2    = (const float*)d_in[26];

    float* out_ls = (float*)d_out;
    float* out_w  = out_ls + (size_t)NN * OUTC;
    float* out_lr = out_w + EE;

    const int NB   = (NN + 255) / 256;
    const int EB   = (EE + 255) / 256;
    const int WRPN = (NN * 32) / 256;
    const int WRPE = (EE * 32) / 256;
    const int GEMG = (NN + 63) / 64;

    // ---- fork: CSR build on side stream, GEMMs on main stream ----
    cudaStream_t s1str;
    cudaEvent_t evFork, evJoin;
    cudaStreamCreateWithFlags(&s1str, cudaStreamNonBlocking);
    cudaEventCreateWithFlags(&evFork, cudaEventDisableTiming);
    cudaEventCreateWithFlags(&evJoin, cudaEventDisableTiming);

    cudaEventRecord(evFork, 0);
    cudaStreamWaitEvent(s1str, evFork, 0);

    // side stream: CSR build chain
    init_kernel<<<NB, 256, 0, s1str>>>(cnt1, cnt2, flag64, stat);
    detect_kernel<<<256, 256, 0, s1str>>>(eiw, flag64);
    convert_hist_kernel<<<EB, 256, 0, s1str>>>(eiw, flag64, rowA, colA, cnt1, cnt2);
    scan_p1<<<dim3(NTILE, 2), 256, 0, s1str>>>(cnt1, cnt2, btot);
    scan_p2<<<dim3(1, 2), 256, 0, s1str>>>(btot);
    scan_p3<<<dim3(NTILE, 2), 256, 0, s1str>>>(cnt1, cnt2, btot, off1, off2, cur1, cur2, csr1);
    fill_kernel<<<EB, 256, 0, s1str>>>(rowA, colA, cur1, csr1, cur2, csr2c, csr2e);
    cudaEventRecord(evJoin, s1str);

    // main stream: weight fusion, then fused h1 GEMM (+attention dots)
    wfuse_kernel<<<128, 128>>>(Wg1, W_res, b_res, Wf, bf);
    gemm_k128<128, false, true, false, false><<<GEMG, 128>>>(
        x, Wf, 128, 0, bf, bufH, 128, 0, NN,
        nullptr, nullptr, nullptr, nullptr, as1, ad1, asrc, adst, nullptr, nullptr);

    // join: aggregation needs CSR + stats-zeroing from side stream
    cudaStreamWaitEvent(0, evJoin, 0);

    gat_aggregate<<<WRPN, 256>>>(bufH, asrc, adst, off1, csr1, bg1, bufG, s1s, s1q);
    bn_finalize<<<1, 128>>>(s1s, s1q, mean1, rstd1, 128);

    // GAT layer 2 (BN+ELU of layer1 fused into A-load)
    gemm_k128<128, true, true, false, false><<<GEMG, 128>>>(
        bufG, Wg2, 128, 0, nullptr, bufH, 128, 0, NN,
        mean1, rstd1, g1, be1, as2, ad2, asrc, adst, nullptr, nullptr);
    gat_aggregate<<<WRPN, 256>>>(bufH, asrc, adst, off1, csr1, bg2, bufG, s2s, s2q);
    bn_finalize<<<1, 128>>>(s2s, s2q, mean2, rstd2, 128);
    bn_elu_kernel<<<(NN * 32 + 255) / 256, 256>>>(bufG, mean2, rstd2, g2, be2, bufA, NN * 128);
    // bufA = h_base

    // edge scorer: single merged SPLITW GEMM (pr | pc)
    gemm_k128<128, false, false, false, true><<<GEMG, 128>>>(
        bufA, Ws1, 256, 0, nullptr, bufH, 128, 0, NN,
        nullptr, nullptr, nullptr, nullptr, nullptr, nullptr, nullptr, nullptr, nullptr, nullptr);
    edge_logits_kernel<<<WRPE, 256>>>(bufH, rowA, colA, gumbel, bs1, Ws2, bs2, out_w, out_lr);

    // sparse aggregation
    sparse_agg_kernel<<<WRPN, 256>>>(bufA, off2, csr2c, csr2e, out_w, bufG);

    // classifier (BN stats fused into GEMM)
    gemm_k128<64, false, false, true, false><<<GEMG, 128>>>(
        bufG, Wc1, 128, 0, bc1, bufC, 64, 0, NN,
        nullptr, nullptr, nullptr, nullptr, nullptr, nullptr, nullptr, nullptr, scs, scq);
    bn_finalize<<<1, 64>>>(scs, scq, meanc, rstdc, 64);
    classifier_kernel<<<WRPN, 256>>>(bufC, meanc, rstdc, gc, bec, Wc2, bc2, out_ls);
}